// round 1
// baseline (speedup 1.0000x reference)
#include <cuda_runtime.h>
#include <cstdint>

// Problem constants
#define N_LINES   8192
#define D_MODEL   768
#define H_HEADS   8
#define HD        96          // head dim
#define OVERLAP   32
#define GAP       4
#define W_KEYS    16
#define M_COMB    (N_LINES + 2*OVERLAP)   // 8256
#define QKV_N     (3*D_MODEL)             // 2304

// Scratch (device globals: allocation-free rule)
__device__ float g_comb[(size_t)M_COMB * D_MODEL];        // combined rows
__device__ float g_P[(size_t)M_COMB * QKV_N];             // QKV projections
__device__ float g_ctx[(size_t)N_LINES * D_MODEL];        // attention context

// ---------------------------------------------------------------------------
// build combined = [begin; main; end]   (float4 copies)
// ---------------------------------------------------------------------------
__global__ void build_combined(const float* __restrict__ mn,
                               const float* __restrict__ bg,
                               const float* __restrict__ ed)
{
    int i = blockIdx.x * blockDim.x + threadIdx.x;       // float4 index
    const int total = M_COMB * D_MODEL / 4;
    if (i >= total) return;
    int row = i / (D_MODEL/4);
    int c4  = i % (D_MODEL/4);
    const float4* src;
    if (row < OVERLAP)               src = (const float4*)(bg + (size_t)row * D_MODEL);
    else if (row < OVERLAP+N_LINES)  src = (const float4*)(mn + (size_t)(row-OVERLAP) * D_MODEL);
    else                             src = (const float4*)(ed + (size_t)(row-OVERLAP-N_LINES) * D_MODEL);
    ((float4*)g_comb)[i] = src[c4];
}

// ---------------------------------------------------------------------------
// copy main into d_out[:, 0:768]  (row stride 1536)
// ---------------------------------------------------------------------------
__global__ void copy_main(const float* __restrict__ mn, float* __restrict__ out)
{
    int i = blockIdx.x * blockDim.x + threadIdx.x;       // float4 index
    const int total = N_LINES * D_MODEL / 4;
    if (i >= total) return;
    int row = i / (D_MODEL/4);
    int c4  = i % (D_MODEL/4);
    ((float4*)(out + (size_t)row * 2 * D_MODEL))[c4] =
        ((const float4*)(mn + (size_t)row * D_MODEL))[c4];
}

// ---------------------------------------------------------------------------
// SGEMM: C[m, coff+n] = sum_k A[m,k] * W[n,k] + bias[n]
// A: M x K row-major, W: N x K row-major, C row stride ldc.
// BM=BN=128, BK=16, 256 threads, 8x8 per thread.
// ---------------------------------------------------------------------------
__global__ __launch_bounds__(256, 2)
void sgemm_nt_bias(int M, int N, int K,
                   const float* __restrict__ A,
                   const float* __restrict__ W,
                   const float* __restrict__ bias,
                   float* __restrict__ C, int ldc, int coff)
{
    const int BM = 128, BN = 128, BK = 16;
    __shared__ float As[BK][BM];
    __shared__ float Ws[BK][BN];

    int tid = threadIdx.x;
    int bm = blockIdx.y * BM;
    int bn = blockIdx.x * BN;

    int lRow = tid >> 2;           // 0..63
    int lCol = (tid & 3) << 2;     // 0,4,8,12

    float acc[8][8];
    #pragma unroll
    for (int i = 0; i < 8; i++)
        #pragma unroll
        for (int j = 0; j < 8; j++) acc[i][j] = 0.f;

    int tr = (tid >> 4) << 3;      // 0..120
    int tc = (tid & 15) << 3;

    for (int k0 = 0; k0 < K; k0 += BK) {
        #pragma unroll
        for (int r = 0; r < 2; r++) {
            int m = bm + lRow + r*64;
            float4 v = make_float4(0.f,0.f,0.f,0.f);
            if (m < M) v = *(const float4*)(A + (size_t)m*K + k0 + lCol);
            As[lCol+0][lRow + r*64] = v.x;
            As[lCol+1][lRow + r*64] = v.y;
            As[lCol+2][lRow + r*64] = v.z;
            As[lCol+3][lRow + r*64] = v.w;
        }
        #pragma unroll
        for (int r = 0; r < 2; r++) {
            int n = bn + lRow + r*64;
            float4 v = make_float4(0.f,0.f,0.f,0.f);
            if (n < N) v = *(const float4*)(W + (size_t)n*K + k0 + lCol);
            Ws[lCol+0][lRow + r*64] = v.x;
            Ws[lCol+1][lRow + r*64] = v.y;
            Ws[lCol+2][lRow + r*64] = v.z;
            Ws[lCol+3][lRow + r*64] = v.w;
        }
        __syncthreads();

        #pragma unroll
        for (int kk = 0; kk < BK; kk++) {
            float ra[8], rb[8];
            #pragma unroll
            for (int i = 0; i < 8; i++) ra[i] = As[kk][tr + i];
            #pragma unroll
            for (int j = 0; j < 8; j++) rb[j] = Ws[kk][tc + j];
            #pragma unroll
            for (int i = 0; i < 8; i++)
                #pragma unroll
                for (int j = 0; j < 8; j++)
                    acc[i][j] = fmaf(ra[i], rb[j], acc[i][j]);
        }
        __syncthreads();
    }

    #pragma unroll
    for (int i = 0; i < 8; i++) {
        int m = bm + tr + i;
        if (m >= M) break;
        float* crow = C + (size_t)m * ldc + coff;
        #pragma unroll
        for (int j = 0; j < 8; j++) {
            int n = bn + tc + j;
            if (n < N) crow[n] = acc[i][j] + bias[n];
        }
    }
}

// ---------------------------------------------------------------------------
// Attention: one block per line n, one warp per head.
// q = P[n+32, h*96 : ] * hd^-0.5 ; keys/values gathered at strided offsets.
// ---------------------------------------------------------------------------
__global__ __launch_bounds__(256)
void attn_kernel(const float* __restrict__ P, float* __restrict__ ctx)
{
    int n    = blockIdx.x;
    int h    = threadIdx.x >> 5;
    int lane = threadIdx.x & 31;

    const float scale = rsqrtf((float)HD);
    const float* qrow = P + (size_t)(n + OVERLAP) * QKV_N + h * HD;
    float q0 = qrow[lane]      * scale;
    float q1 = qrow[lane + 32] * scale;
    float q2 = qrow[lane + 64] * scale;

    float s[W_KEYS];
    #pragma unroll
    for (int w = 0; w < W_KEYS; w++) {
        int off = (w < 8) ? (-OVERLAP + GAP * w) : (GAP * (w - 7));
        const float* krow = P + (size_t)(n + OVERLAP + off) * QKV_N + D_MODEL + h * HD;
        float p = q0 * krow[lane] + q1 * krow[lane + 32] + q2 * krow[lane + 64];
        #pragma unroll
        for (int d = 16; d > 0; d >>= 1) p += __shfl_xor_sync(0xffffffffu, p, d);
        s[w] = p;
    }

    float m = s[0];
    #pragma unroll
    for (int w = 1; w < W_KEYS; w++) m = fmaxf(m, s[w]);
    float sum = 0.f;
    #pragma unroll
    for (int w = 0; w < W_KEYS; w++) { s[w] = expf(s[w] - m); sum += s[w]; }
    float inv = 1.f / sum;

    float a0 = 0.f, a1 = 0.f, a2 = 0.f;
    #pragma unroll
    for (int w = 0; w < W_KEYS; w++) {
        int off = (w < 8) ? (-OVERLAP + GAP * w) : (GAP * (w - 7));
        const float* vrow = P + (size_t)(n + OVERLAP + off) * QKV_N + 2 * D_MODEL + h * HD;
        float p = s[w] * inv;
        a0 = fmaf(p, vrow[lane],      a0);
        a1 = fmaf(p, vrow[lane + 32], a1);
        a2 = fmaf(p, vrow[lane + 64], a2);
    }

    float* c = ctx + (size_t)n * D_MODEL + h * HD;
    c[lane]      = a0;
    c[lane + 32] = a1;
    c[lane + 64] = a2;
}

// ---------------------------------------------------------------------------
extern "C" void kernel_launch(void* const* d_in, const int* in_sizes, int n_in,
                              void* d_out, int out_size)
{
    const float* mn  = (const float*)d_in[0];   // main   (8192,768)
    const float* bg  = (const float*)d_in[1];   // begin  (32,768)
    const float* ed  = (const float*)d_in[2];   // end    (32,768)
    const float* wqkv= (const float*)d_in[3];   // in_proj_w (2304,768)
    const float* bqkv= (const float*)d_in[4];   // in_proj_b (2304)
    const float* wo  = (const float*)d_in[5];   // out_proj_w (768,768)
    const float* bo  = (const float*)d_in[6];   // out_proj_b (768)
    float* out = (float*)d_out;                 // (8192, 1536)

    void *p_comb, *p_P, *p_ctx;
    cudaGetSymbolAddress(&p_comb, g_comb);
    cudaGetSymbolAddress(&p_P,    g_P);
    cudaGetSymbolAddress(&p_ctx,  g_ctx);
    float* comb = (float*)p_comb;
    float* P    = (float*)p_P;
    float* ctx  = (float*)p_ctx;

    // 1. combined
    {
        int total = M_COMB * D_MODEL / 4;
        build_combined<<<(total + 255) / 256, 256>>>(mn, bg, ed);
    }
    // 2. copy main into out[:, :768] (independent; overlap with GEMM below)
    {
        int total = N_LINES * D_MODEL / 4;
        copy_main<<<(total + 255) / 256, 256>>>(mn, out);
    }
    // 3. QKV projection: P = comb @ wqkv^T + bqkv   (M=8256, N=2304, K=768)
    {
        dim3 grid(QKV_N / 128, (M_COMB + 127) / 128);
        sgemm_nt_bias<<<grid, 256>>>(M_COMB, QKV_N, D_MODEL,
                                     comb, wqkv, bqkv, P, QKV_N, 0);
    }
    // 4. attention -> ctx
    attn_kernel<<<N_LINES, 256>>>(P, ctx);

    // 5. out proj: out[:, 768:1536] = ctx @ wo^T + bo  (M=8192, N=768, K=768)
    {
        dim3 grid(D_MODEL / 128, N_LINES / 128);
        sgemm_nt_bias<<<grid, 256>>>(N_LINES, D_MODEL, D_MODEL,
                                     ctx, wo, bo, out, 2 * D_MODEL, D_MODEL);
    }
}

// round 3
// speedup vs baseline: 2.4651x; 2.4651x over previous
#include <cuda_runtime.h>
#include <cuda_bf16.h>
#include <cstdint>

#define N_LINES   8192
#define D_MODEL   768
#define HD        96
#define OVERLAP   32
#define GAP       4
#define W_KEYS    16
#define M_COMB    (N_LINES + 2*OVERLAP)   // 8256
#define QKV_N     (3*D_MODEL)             // 2304
#define KDIM      768
#define BK        32
#define CHUNKS    (KDIM / BK)             // 24

// ---- scratch (device globals) ----
__device__ __nv_bfloat16 g_comb_h[(size_t)M_COMB * KDIM];
__device__ __nv_bfloat16 g_comb_l[(size_t)M_COMB * KDIM];
__device__ float         g_P[(size_t)M_COMB * QKV_N];
__device__ __nv_bfloat16 g_w1_h[(size_t)QKV_N * KDIM];
__device__ __nv_bfloat16 g_w1_l[(size_t)QKV_N * KDIM];
__device__ __nv_bfloat16 g_w2_h[(size_t)D_MODEL * KDIM];
__device__ __nv_bfloat16 g_w2_l[(size_t)D_MODEL * KDIM];
__device__ __nv_bfloat16 g_ctx_h[(size_t)N_LINES * KDIM];
__device__ __nv_bfloat16 g_ctx_l[(size_t)N_LINES * KDIM];

// ---------------- PTX helpers ----------------
__device__ __forceinline__ uint32_t smem_u32(const void* p) {
    uint32_t a;
    asm("{ .reg .u64 t; cvta.to.shared.u64 t, %1; cvt.u32.u64 %0, t; }" : "=r"(a) : "l"(p));
    return a;
}

#define CP_ASYNC16(s, g, sz) \
    asm volatile("cp.async.cg.shared.global [%0], [%1], 16, %2;" :: "r"(s), "l"(g), "r"(sz))
#define CP_COMMIT() asm volatile("cp.async.commit_group;")
#define CP_WAIT0()  asm volatile("cp.async.wait_group 0;")

#define LDSM4(r, addr) \
    asm volatile("ldmatrix.sync.aligned.m8n8.x4.shared.b16 {%0,%1,%2,%3}, [%4];" \
        : "=r"((r)[0]), "=r"((r)[1]), "=r"((r)[2]), "=r"((r)[3]) : "r"(addr))

#define MMA16816(d, a, b0, b1) \
    asm volatile("mma.sync.aligned.m16n8k16.row.col.f32.bf16.bf16.f32 " \
        "{%0,%1,%2,%3}, {%4,%5,%6,%7}, {%8,%9}, {%0,%1,%2,%3};" \
        : "+f"((d)[0]), "+f"((d)[1]), "+f"((d)[2]), "+f"((d)[3]) \
        : "r"((a)[0]), "r"((a)[1]), "r"((a)[2]), "r"((a)[3]), "r"(b0), "r"(b1))

// swizzled 16B-chunk offset within a [row][64B] tile
__device__ __forceinline__ uint32_t swz_off(int row, int chunk) {
    return (uint32_t)(row * 64 + ((chunk ^ ((row >> 1) & 3)) << 4));
}

// ---------------------------------------------------------------------------
// prep kernels
// ---------------------------------------------------------------------------
__global__ void build_comb_split(const float* __restrict__ mn,
                                 const float* __restrict__ bg,
                                 const float* __restrict__ ed)
{
    int i = blockIdx.x * blockDim.x + threadIdx.x;
    const int total = M_COMB * KDIM;
    if (i >= total) return;
    int row = i / KDIM, c = i % KDIM;
    float x;
    if (row < OVERLAP)                x = bg[(size_t)row * KDIM + c];
    else if (row < OVERLAP + N_LINES) x = mn[(size_t)(row - OVERLAP) * KDIM + c];
    else                              x = ed[(size_t)(row - OVERLAP - N_LINES) * KDIM + c];
    __nv_bfloat16 h = __float2bfloat16_rn(x);
    g_comb_h[i] = h;
    g_comb_l[i] = __float2bfloat16_rn(x - __bfloat162float(h));
}

__global__ void split_fp32(const float* __restrict__ in,
                           __nv_bfloat16* __restrict__ hi,
                           __nv_bfloat16* __restrict__ lo, int n)
{
    int i = blockIdx.x * blockDim.x + threadIdx.x;
    if (i >= n) return;
    float x = in[i];
    __nv_bfloat16 h = __float2bfloat16_rn(x);
    hi[i] = h;
    lo[i] = __float2bfloat16_rn(x - __bfloat162float(h));
}

__global__ void copy_main(const float* __restrict__ mn, float* __restrict__ out)
{
    int i = blockIdx.x * blockDim.x + threadIdx.x;
    const int total = N_LINES * D_MODEL / 4;
    if (i >= total) return;
    int row = i / (D_MODEL/4), c4 = i % (D_MODEL/4);
    ((float4*)(out + (size_t)row * 2 * D_MODEL))[c4] =
        ((const float4*)(mn + (size_t)row * D_MODEL))[c4];
}

// ---------------------------------------------------------------------------
// HMMA GEMM, 3-pass bf16 split: C[m, coff+n] = sum_k A[m,k]*W[n,k] + bias[n]
// BM=128, BN=128, BK=32, 256 threads (8 warps, 2x4), warp tile 64x32.
// Double-buffered cp.async stages (Ah/Al/Bh/Bl @ 8KB each = 32KB/stage).
// ---------------------------------------------------------------------------
#define STAGE_BYTES 32768
#define GEMM_SMEM   (2 * STAGE_BYTES)

struct GArgs { const __nv_bfloat16 *Ah, *Al, *Bh, *Bl; };

__device__ __forceinline__ void load_stage(uint32_t smb, int stage,
                                           const GArgs& g, int bm, int bn,
                                           int k0, int M, int tid)
{
    const uint32_t base = smb + stage * STAGE_BYTES;
    #pragma unroll
    for (int i = 0; i < 2; i++) {
        int idx = tid + i * 256;           // 0..511
        int row = idx >> 2, c = idx & 3;
        uint32_t so = swz_off(row, c);
        // A (rows may be OOB on last M tile -> zero-fill)
        int m = bm + row;
        int msz = (m < M) ? 16 : 0;
        int mc = (m < M) ? m : (M - 1);
        const char* gah = (const char*)(g.Ah + (size_t)mc * KDIM + k0 + c * 8);
        const char* gal = (const char*)(g.Al + (size_t)mc * KDIM + k0 + c * 8);
        CP_ASYNC16(base + so,         gah, msz);
        CP_ASYNC16(base + 8192 + so,  gal, msz);
        // B (N multiple of 128, always in range)
        int n = bn + row;
        const char* gbh = (const char*)(g.Bh + (size_t)n * KDIM + k0 + c * 8);
        const char* gbl = (const char*)(g.Bl + (size_t)n * KDIM + k0 + c * 8);
        CP_ASYNC16(base + 16384 + so, gbh, 16);
        CP_ASYNC16(base + 24576 + so, gbl, 16);
    }
}

__global__ __launch_bounds__(256, 1)
void gemm_bf16x3(int M,
                 const __nv_bfloat16* __restrict__ Ah, const __nv_bfloat16* __restrict__ Al,
                 const __nv_bfloat16* __restrict__ Bh, const __nv_bfloat16* __restrict__ Bl,
                 const float* __restrict__ bias,
                 float* __restrict__ C, int ldc, int coff)
{
    extern __shared__ char sm[];
    const uint32_t smb = smem_u32(sm);
    const int tid  = threadIdx.x;
    const int lane = tid & 31;
    const int wid  = tid >> 5;
    const int wm   = wid & 1;       // 2 warps over M
    const int wn   = wid >> 1;      // 4 warps over N
    const int bm = blockIdx.y * 128;
    const int bn = blockIdx.x * 128;

    GArgs g{Ah, Al, Bh, Bl};

    float acc[4][4][4];
    #pragma unroll
    for (int i = 0; i < 4; i++)
        #pragma unroll
        for (int j = 0; j < 4; j++)
            #pragma unroll
            for (int r = 0; r < 4; r++) acc[i][j][r] = 0.f;

    load_stage(smb, 0, g, bm, bn, 0, M, tid);
    CP_COMMIT();
    CP_WAIT0();
    __syncthreads();

    // per-lane ldmatrix address components
    const int lane15 = lane & 15;
    const int aChunkSel = lane >> 4;              // A: lanes 0-15 chunk+0, 16-31 chunk+1
    const int bRow = ((lane & 16) >> 1) + (lane & 7);   // 0-7,0-7,8-15,8-15
    const int bChunkSel = (lane >> 3) & 1;        // 0,1,0,1

    for (int c = 0; c < CHUNKS; c++) {
        const uint32_t base = smb + (c & 1) * STAGE_BYTES;
        if (c + 1 < CHUNKS) {
            load_stage(smb, (c + 1) & 1, g, bm, bn, (c + 1) * BK, M, tid);
            CP_COMMIT();
        }

        #pragma unroll
        for (int ks = 0; ks < 2; ks++) {
            const int c0 = ks * 2;
            uint32_t ah[4][4], al[4][4], bh[2][4], bl[2][4];
            #pragma unroll
            for (int mt = 0; mt < 4; mt++) {
                int row = wm * 64 + mt * 16 + lane15;
                uint32_t so = swz_off(row, c0 + aChunkSel);
                LDSM4(ah[mt], base + so);
                LDSM4(al[mt], base + 8192 + so);
            }
            #pragma unroll
            for (int bt = 0; bt < 2; bt++) {
                int row = wn * 32 + bt * 16 + bRow;
                uint32_t so = swz_off(row, c0 + bChunkSel);
                LDSM4(bh[bt], base + 16384 + so);
                LDSM4(bl[bt], base + 24576 + so);
            }
            #pragma unroll
            for (int mt = 0; mt < 4; mt++) {
                #pragma unroll
                for (int nt = 0; nt < 4; nt++) {
                    const uint32_t* bhp = bh[nt >> 1] + ((nt & 1) << 1);
                    const uint32_t* blp = bl[nt >> 1] + ((nt & 1) << 1);
                    MMA16816(acc[mt][nt], ah[mt], bhp[0], bhp[1]);   // Ah*Bh
                    MMA16816(acc[mt][nt], al[mt], bhp[0], bhp[1]);   // Al*Bh
                    MMA16816(acc[mt][nt], ah[mt], blp[0], blp[1]);   // Ah*Bl
                }
            }
        }

        if (c + 1 < CHUNKS) {
            CP_WAIT0();
            __syncthreads();
        }
    }

    // epilogue
    #pragma unroll
    for (int mt = 0; mt < 4; mt++) {
        int m0 = bm + wm * 64 + mt * 16 + (lane >> 2);
        #pragma unroll
        for (int nt = 0; nt < 4; nt++) {
            int n = bn + wn * 32 + nt * 8 + (lane & 3) * 2;
            float bx = bias[n], by = bias[n + 1];
            if (m0 < M) {
                float2 v = make_float2(acc[mt][nt][0] + bx, acc[mt][nt][1] + by);
                *(float2*)(C + (size_t)m0 * ldc + coff + n) = v;
            }
            if (m0 + 8 < M) {
                float2 v = make_float2(acc[mt][nt][2] + bx, acc[mt][nt][3] + by);
                *(float2*)(C + (size_t)(m0 + 8) * ldc + coff + n) = v;
            }
        }
    }
}

// ---------------------------------------------------------------------------
// Attention: one block per line, one warp per head. Emits bf16 hi/lo ctx.
// ---------------------------------------------------------------------------
__global__ __launch_bounds__(256)
void attn_kernel(const float* __restrict__ P,
                 __nv_bfloat16* __restrict__ ctxh, __nv_bfloat16* __restrict__ ctxl)
{
    int n = blockIdx.x;
    int h = threadIdx.x >> 5;
    int lane = threadIdx.x & 31;

    const float scale = rsqrtf((float)HD);
    const float* qrow = P + (size_t)(n + OVERLAP) * QKV_N + h * HD;
    float q0 = qrow[lane] * scale, q1 = qrow[lane+32] * scale, q2 = qrow[lane+64] * scale;

    float s[W_KEYS];
    #pragma unroll
    for (int w = 0; w < W_KEYS; w++) {
        int off = (w < 8) ? (-OVERLAP + GAP * w) : (GAP * (w - 7));
        const float* krow = P + (size_t)(n + OVERLAP + off) * QKV_N + D_MODEL + h * HD;
        float p = q0*krow[lane] + q1*krow[lane+32] + q2*krow[lane+64];
        #pragma unroll
        for (int d = 16; d > 0; d >>= 1) p += __shfl_xor_sync(0xffffffffu, p, d);
        s[w] = p;
    }
    float m = s[0];
    #pragma unroll
    for (int w = 1; w < W_KEYS; w++) m = fmaxf(m, s[w]);
    float sum = 0.f;
    #pragma unroll
    for (int w = 0; w < W_KEYS; w++) { s[w] = expf(s[w] - m); sum += s[w]; }
    float inv = 1.f / sum;

    float a0 = 0.f, a1 = 0.f, a2 = 0.f;
    #pragma unroll
    for (int w = 0; w < W_KEYS; w++) {
        int off = (w < 8) ? (-OVERLAP + GAP * w) : (GAP * (w - 7));
        const float* vrow = P + (size_t)(n + OVERLAP + off) * QKV_N + 2*D_MODEL + h * HD;
        float p = s[w] * inv;
        a0 = fmaf(p, vrow[lane],    a0);
        a1 = fmaf(p, vrow[lane+32], a1);
        a2 = fmaf(p, vrow[lane+64], a2);
    }

    size_t o = (size_t)n * D_MODEL + h * HD;
    __nv_bfloat16 h0 = __float2bfloat16_rn(a0);
    __nv_bfloat16 h1 = __float2bfloat16_rn(a1);
    __nv_bfloat16 h2 = __float2bfloat16_rn(a2);
    ctxh[o + lane]    = h0; ctxl[o + lane]    = __float2bfloat16_rn(a0 - __bfloat162float(h0));
    ctxh[o + lane+32] = h1; ctxl[o + lane+32] = __float2bfloat16_rn(a1 - __bfloat162float(h1));
    ctxh[o + lane+64] = h2; ctxl[o + lane+64] = __float2bfloat16_rn(a2 - __bfloat162float(h2));
}

// ---------------------------------------------------------------------------
extern "C" void kernel_launch(void* const* d_in, const int* in_sizes, int n_in,
                              void* d_out, int out_size)
{
    const float* mn   = (const float*)d_in[0];
    const float* bg   = (const float*)d_in[1];
    const float* ed   = (const float*)d_in[2];
    const float* wqkv = (const float*)d_in[3];
    const float* bqkv = (const float*)d_in[4];
    const float* wo   = (const float*)d_in[5];
    const float* bo   = (const float*)d_in[6];
    float* out = (float*)d_out;

    void *pP, *pch, *pcl, *pw1h, *pw1l, *pw2h, *pw2l, *pcxh, *pcxl;
    cudaGetSymbolAddress(&pP,  g_P);
    cudaGetSymbolAddress(&pch, g_comb_h);  cudaGetSymbolAddress(&pcl, g_comb_l);
    cudaGetSymbolAddress(&pw1h, g_w1_h);   cudaGetSymbolAddress(&pw1l, g_w1_l);
    cudaGetSymbolAddress(&pw2h, g_w2_h);   cudaGetSymbolAddress(&pw2l, g_w2_l);
    cudaGetSymbolAddress(&pcxh, g_ctx_h);  cudaGetSymbolAddress(&pcxl, g_ctx_l);
    float* P = (float*)pP;

    cudaFuncSetAttribute(gemm_bf16x3, cudaFuncAttributeMaxDynamicSharedMemorySize, GEMM_SMEM);

    // prep
    {
        int t1 = M_COMB * KDIM;
        build_comb_split<<<(t1 + 255) / 256, 256>>>(mn, bg, ed);
        int t2 = QKV_N * KDIM;
        split_fp32<<<(t2 + 255) / 256, 256>>>(wqkv, (__nv_bfloat16*)pw1h, (__nv_bfloat16*)pw1l, t2);
        int t3 = D_MODEL * KDIM;
        split_fp32<<<(t3 + 255) / 256, 256>>>(wo, (__nv_bfloat16*)pw2h, (__nv_bfloat16*)pw2l, t3);
        int t4 = N_LINES * D_MODEL / 4;
        copy_main<<<(t4 + 255) / 256, 256>>>(mn, out);
    }
    // GEMM1: P = comb @ wqkv^T + bqkv  (M=8256, N=2304)
    {
        dim3 grid(QKV_N / 128, (M_COMB + 127) / 128);
        gemm_bf16x3<<<grid, 256, GEMM_SMEM>>>(M_COMB,
            (const __nv_bfloat16*)pch, (const __nv_bfloat16*)pcl,
            (const __nv_bfloat16*)pw1h, (const __nv_bfloat16*)pw1l,
            bqkv, P, QKV_N, 0);
    }
    // attention -> ctx (bf16 hi/lo)
    attn_kernel<<<N_LINES, 256>>>(P, (__nv_bfloat16*)pcxh, (__nv_bfloat16*)pcxl);

    // GEMM2: out[:,768:] = ctx @ wo^T + bo  (M=8192, N=768)
    {
        dim3 grid(D_MODEL / 128, N_LINES / 128);
        gemm_bf16x3<<<grid, 256, GEMM_SMEM>>>(N_LINES,
            (const __nv_bfloat16*)pcxh, (const __nv_bfloat16*)pcxl,
            (const __nv_bfloat16*)pw2h, (const __nv_bfloat16*)pw2l,
            bo, out, 2 * D_MODEL, D_MODEL);
    }
}

// round 4
// speedup vs baseline: 3.9850x; 1.6166x over previous
#include <cuda_runtime.h>
#include <cuda_fp16.h>
#include <cstdint>

#define N_LINES   8192
#define D_MODEL   768
#define HD        96
#define OVERLAP   32
#define GAP       4
#define W_KEYS    16
#define M_COMB    (N_LINES + 2*OVERLAP)   // 8256
#define QKV_N     (3*D_MODEL)             // 2304
#define KDIM      768
#define BK        32
#define CHUNKS    (KDIM / BK)             // 24

// ---- scratch (device globals) ----
__device__ __half g_comb[(size_t)M_COMB * KDIM];
__device__ __half g_P[(size_t)M_COMB * QKV_N];
__device__ __half g_w1[(size_t)QKV_N * KDIM];
__device__ __half g_w2[(size_t)D_MODEL * KDIM];
__device__ __half g_ctx[(size_t)N_LINES * KDIM];

// ---------------- PTX helpers ----------------
__device__ __forceinline__ uint32_t smem_u32(const void* p) {
    uint32_t a;
    asm("{ .reg .u64 t; cvta.to.shared.u64 t, %1; cvt.u32.u64 %0, t; }" : "=r"(a) : "l"(p));
    return a;
}

#define CP_ASYNC16(s, g, sz) \
    asm volatile("cp.async.cg.shared.global [%0], [%1], 16, %2;" :: "r"(s), "l"(g), "r"(sz))
#define CP_COMMIT() asm volatile("cp.async.commit_group;")
#define CP_WAIT0()  asm volatile("cp.async.wait_group 0;")

#define LDSM4(r, addr) \
    asm volatile("ldmatrix.sync.aligned.m8n8.x4.shared.b16 {%0,%1,%2,%3}, [%4];" \
        : "=r"((r)[0]), "=r"((r)[1]), "=r"((r)[2]), "=r"((r)[3]) : "r"(addr))

#define MMA16816(d, a, b0, b1) \
    asm volatile("mma.sync.aligned.m16n8k16.row.col.f32.f16.f16.f32 " \
        "{%0,%1,%2,%3}, {%4,%5,%6,%7}, {%8,%9}, {%0,%1,%2,%3};" \
        : "+f"((d)[0]), "+f"((d)[1]), "+f"((d)[2]), "+f"((d)[3]) \
        : "r"((a)[0]), "r"((a)[1]), "r"((a)[2]), "r"((a)[3]), "r"(b0), "r"(b1))

// swizzled 16B-chunk offset within a [row][64B] tile
__device__ __forceinline__ uint32_t swz_off(int row, int chunk) {
    return (uint32_t)(row * 64 + ((chunk ^ ((row >> 1) & 3)) << 4));
}

// ---------------------------------------------------------------------------
// prep kernels
// ---------------------------------------------------------------------------
__global__ void build_comb_h(const float* __restrict__ mn,
                             const float* __restrict__ bg,
                             const float* __restrict__ ed)
{
    int i = blockIdx.x * blockDim.x + threadIdx.x;
    const int total = M_COMB * KDIM;
    if (i >= total) return;
    int row = i / KDIM, c = i % KDIM;
    float x;
    if (row < OVERLAP)                x = bg[(size_t)row * KDIM + c];
    else if (row < OVERLAP + N_LINES) x = mn[(size_t)(row - OVERLAP) * KDIM + c];
    else                              x = ed[(size_t)(row - OVERLAP - N_LINES) * KDIM + c];
    g_comb[i] = __float2half_rn(x);
}

__global__ void to_half(const float* __restrict__ in, __half* __restrict__ o, int n)
{
    int i = blockIdx.x * blockDim.x + threadIdx.x;
    if (i >= n) return;
    o[i] = __float2half_rn(in[i]);
}

__global__ void copy_main(const float* __restrict__ mn, float* __restrict__ out)
{
    int i = blockIdx.x * blockDim.x + threadIdx.x;
    const int total = N_LINES * D_MODEL / 4;
    if (i >= total) return;
    int row = i / (D_MODEL/4), c4 = i % (D_MODEL/4);
    ((float4*)(out + (size_t)row * 2 * D_MODEL))[c4] =
        ((const float4*)(mn + (size_t)row * D_MODEL))[c4];
}

// ---------------------------------------------------------------------------
// HMMA GEMM fp16 single-pass: C[m, coff+n] = sum_k A[m,k]*W[n,k] + bias[n]
// BM=128, BN=128, BK=32, 256 threads (8 warps, 2x4), warp tile 64x32.
// Double-buffered cp.async stages (A 8KB + B 8KB = 16KB/stage).
// HALF_OUT: write __half C, else float C.
// ---------------------------------------------------------------------------
#define STAGE_BYTES 16384
#define GEMM_SMEM   (2 * STAGE_BYTES)

__device__ __forceinline__ void load_stage(uint32_t smb, int stage,
                                           const __half* A, const __half* B,
                                           int bm, int bn, int k0, int M, int tid)
{
    const uint32_t base = smb + stage * STAGE_BYTES;
    #pragma unroll
    for (int i = 0; i < 2; i++) {
        int idx = tid + i * 256;           // 0..511
        int row = idx >> 2, c = idx & 3;
        uint32_t so = swz_off(row, c);
        int m = bm + row;
        int msz = (m < M) ? 16 : 0;
        int mc = (m < M) ? m : (M - 1);
        const char* ga = (const char*)(A + (size_t)mc * KDIM + k0 + c * 8);
        CP_ASYNC16(base + so, ga, msz);
        int n = bn + row;
        const char* gb = (const char*)(B + (size_t)n * KDIM + k0 + c * 8);
        CP_ASYNC16(base + 8192 + so, gb, 16);
    }
}

template <bool HALF_OUT>
__global__ __launch_bounds__(256, 1)
void gemm_fp16(int M,
               const __half* __restrict__ A, const __half* __restrict__ B,
               const float* __restrict__ bias,
               void* __restrict__ Cv, int ldc, int coff)
{
    extern __shared__ char sm[];
    const uint32_t smb = smem_u32(sm);
    const int tid  = threadIdx.x;
    const int lane = tid & 31;
    const int wid  = tid >> 5;
    const int wm   = wid & 1;       // 2 warps over M
    const int wn   = wid >> 1;      // 4 warps over N
    const int bm = blockIdx.y * 128;
    const int bn = blockIdx.x * 128;

    float acc[4][4][4];
    #pragma unroll
    for (int i = 0; i < 4; i++)
        #pragma unroll
        for (int j = 0; j < 4; j++)
            #pragma unroll
            for (int r = 0; r < 4; r++) acc[i][j][r] = 0.f;

    load_stage(smb, 0, A, B, bm, bn, 0, M, tid);
    CP_COMMIT();
    CP_WAIT0();
    __syncthreads();

    const int lane15 = lane & 15;
    const int aChunkSel = lane >> 4;
    const int bRow = ((lane & 16) >> 1) + (lane & 7);
    const int bChunkSel = (lane >> 3) & 1;

    for (int c = 0; c < CHUNKS; c++) {
        const uint32_t base = smb + (c & 1) * STAGE_BYTES;
        if (c + 1 < CHUNKS) {
            load_stage(smb, (c + 1) & 1, A, B, bm, bn, (c + 1) * BK, M, tid);
            CP_COMMIT();
        }

        #pragma unroll
        for (int ks = 0; ks < 2; ks++) {
            const int c0 = ks * 2;
            uint32_t af[4][4], bf[2][4];
            #pragma unroll
            for (int mt = 0; mt < 4; mt++) {
                int row = wm * 64 + mt * 16 + lane15;
                LDSM4(af[mt], base + swz_off(row, c0 + aChunkSel));
            }
            #pragma unroll
            for (int bt = 0; bt < 2; bt++) {
                int row = wn * 32 + bt * 16 + bRow;
                LDSM4(bf[bt], base + 8192 + swz_off(row, c0 + bChunkSel));
            }
            #pragma unroll
            for (int mt = 0; mt < 4; mt++)
                #pragma unroll
                for (int nt = 0; nt < 4; nt++) {
                    const uint32_t* bp = bf[nt >> 1] + ((nt & 1) << 1);
                    MMA16816(acc[mt][nt], af[mt], bp[0], bp[1]);
                }
        }

        if (c + 1 < CHUNKS) {
            CP_WAIT0();
            __syncthreads();
        }
    }

    // epilogue
    #pragma unroll
    for (int mt = 0; mt < 4; mt++) {
        int m0 = bm + wm * 64 + mt * 16 + (lane >> 2);
        #pragma unroll
        for (int nt = 0; nt < 4; nt++) {
            int n = bn + wn * 32 + nt * 8 + (lane & 3) * 2;
            float bx = bias[n], by = bias[n + 1];
            if (HALF_OUT) {
                __half* C = (__half*)Cv;
                if (m0 < M) {
                    __half2 v = __floats2half2_rn(acc[mt][nt][0] + bx, acc[mt][nt][1] + by);
                    *(__half2*)(C + (size_t)m0 * ldc + coff + n) = v;
                }
                if (m0 + 8 < M) {
                    __half2 v = __floats2half2_rn(acc[mt][nt][2] + bx, acc[mt][nt][3] + by);
                    *(__half2*)(C + (size_t)(m0 + 8) * ldc + coff + n) = v;
                }
            } else {
                float* C = (float*)Cv;
                if (m0 < M) {
                    float2 v = make_float2(acc[mt][nt][0] + bx, acc[mt][nt][1] + by);
                    *(float2*)(C + (size_t)m0 * ldc + coff + n) = v;
                }
                if (m0 + 8 < M) {
                    float2 v = make_float2(acc[mt][nt][2] + bx, acc[mt][nt][3] + by);
                    *(float2*)(C + (size_t)(m0 + 8) * ldc + coff + n) = v;
                }
            }
        }
    }
}

// ---------------------------------------------------------------------------
// Attention: one block per line, one warp per head. fp16 P in, fp16 ctx out.
// ---------------------------------------------------------------------------
__global__ __launch_bounds__(256)
void attn_kernel(const __half* __restrict__ P, __half* __restrict__ ctx)
{
    int n = blockIdx.x;
    int h = threadIdx.x >> 5;
    int lane = threadIdx.x & 31;

    const float scale = rsqrtf((float)HD);
    const __half* qrow = P + (size_t)(n + OVERLAP) * QKV_N + h * HD;
    float q0 = __half2float(qrow[lane])      * scale;
    float q1 = __half2float(qrow[lane + 32]) * scale;
    float q2 = __half2float(qrow[lane + 64]) * scale;

    float s[W_KEYS];
    #pragma unroll
    for (int w = 0; w < W_KEYS; w++) {
        int off = (w < 8) ? (-OVERLAP + GAP * w) : (GAP * (w - 7));
        const __half* krow = P + (size_t)(n + OVERLAP + off) * QKV_N + D_MODEL + h * HD;
        float p = q0 * __half2float(krow[lane])
                + q1 * __half2float(krow[lane + 32])
                + q2 * __half2float(krow[lane + 64]);
        #pragma unroll
        for (int d = 16; d > 0; d >>= 1) p += __shfl_xor_sync(0xffffffffu, p, d);
        s[w] = p;
    }
    float m = s[0];
    #pragma unroll
    for (int w = 1; w < W_KEYS; w++) m = fmaxf(m, s[w]);
    float sum = 0.f;
    #pragma unroll
    for (int w = 0; w < W_KEYS; w++) { s[w] = expf(s[w] - m); sum += s[w]; }
    float inv = 1.f / sum;

    float a0 = 0.f, a1 = 0.f, a2 = 0.f;
    #pragma unroll
    for (int w = 0; w < W_KEYS; w++) {
        int off = (w < 8) ? (-OVERLAP + GAP * w) : (GAP * (w - 7));
        const __half* vrow = P + (size_t)(n + OVERLAP + off) * QKV_N + 2*D_MODEL + h * HD;
        float p = s[w] * inv;
        a0 = fmaf(p, __half2float(vrow[lane]),      a0);
        a1 = fmaf(p, __half2float(vrow[lane + 32]), a1);
        a2 = fmaf(p, __half2float(vrow[lane + 64]), a2);
    }

    size_t o = (size_t)n * D_MODEL + h * HD;
    ctx[o + lane]      = __float2half_rn(a0);
    ctx[o + lane + 32] = __float2half_rn(a1);
    ctx[o + lane + 64] = __float2half_rn(a2);
}

// ---------------------------------------------------------------------------
extern "C" void kernel_launch(void* const* d_in, const int* in_sizes, int n_in,
                              void* d_out, int out_size)
{
    const float* mn   = (const float*)d_in[0];
    const float* bg   = (const float*)d_in[1];
    const float* ed   = (const float*)d_in[2];
    const float* wqkv = (const float*)d_in[3];
    const float* bqkv = (const float*)d_in[4];
    const float* wo   = (const float*)d_in[5];
    const float* bo   = (const float*)d_in[6];
    float* out = (float*)d_out;

    void *pP, *pc, *pw1, *pw2, *pcx;
    cudaGetSymbolAddress(&pP,  g_P);
    cudaGetSymbolAddress(&pc,  g_comb);
    cudaGetSymbolAddress(&pw1, g_w1);
    cudaGetSymbolAddress(&pw2, g_w2);
    cudaGetSymbolAddress(&pcx, g_ctx);

    cudaFuncSetAttribute(gemm_fp16<true>,  cudaFuncAttributeMaxDynamicSharedMemorySize, GEMM_SMEM);
    cudaFuncSetAttribute(gemm_fp16<false>, cudaFuncAttributeMaxDynamicSharedMemorySize, GEMM_SMEM);

    // prep
    {
        int t1 = M_COMB * KDIM;
        build_comb_h<<<(t1 + 255) / 256, 256>>>(mn, bg, ed);
        int t2 = QKV_N * KDIM;
        to_half<<<(t2 + 255) / 256, 256>>>(wqkv, (__half*)pw1, t2);
        int t3 = D_MODEL * KDIM;
        to_half<<<(t3 + 255) / 256, 256>>>(wo, (__half*)pw2, t3);
        int t4 = N_LINES * D_MODEL / 4;
        copy_main<<<(t4 + 255) / 256, 256>>>(mn, out);
    }
    // GEMM1: P = comb @ wqkv^T + bqkv  (M=8256, N=2304) -> fp16 P
    {
        dim3 grid(QKV_N / 128, (M_COMB + 127) / 128);
        gemm_fp16<true><<<grid, 256, GEMM_SMEM>>>(M_COMB,
            (const __half*)pc, (const __half*)pw1, bqkv, pP, QKV_N, 0);
    }
    // attention -> ctx (fp16)
    attn_kernel<<<N_LINES, 256>>>((const __half*)pP, (__half*)pcx);

    // GEMM2: out[:,768:] = ctx @ wo^T + bo  (M=8192, N=768) -> fp32 out
    {
        dim3 grid(D_MODEL / 128, N_LINES / 128);
        gemm_fp16<false><<<grid, 256, GEMM_SMEM>>>(N_LINES,
            (const __half*)pcx, (const __half*)pw2, bo, out, 2 * D_MODEL, D_MODEL);
    }
}

// round 5
// speedup vs baseline: 4.7376x; 1.1889x over previous
#include <cuda_runtime.h>
#include <cuda_fp16.h>
#include <cstdint>

#define N_LINES   8192
#define D_MODEL   768
#define HD        96
#define OVERLAP   32
#define GAP       4
#define W_KEYS    16
#define M_COMB    (N_LINES + 2*OVERLAP)   // 8256
#define QKV_N     (3*D_MODEL)             // 2304
#define KDIM      768
#define BK        32
#define CHUNKS    (KDIM / BK)             // 24

// ---- scratch (device globals) ----
__device__ __half g_comb[(size_t)M_COMB * KDIM];
__device__ __half g_P[(size_t)M_COMB * QKV_N];
__device__ __half g_w1[(size_t)QKV_N * KDIM];
__device__ __half g_w2[(size_t)D_MODEL * KDIM];
__device__ __half g_ctx[(size_t)N_LINES * KDIM];

// ---------------- PTX helpers ----------------
__device__ __forceinline__ uint32_t smem_u32(const void* p) {
    uint32_t a;
    asm("{ .reg .u64 t; cvta.to.shared.u64 t, %1; cvt.u32.u64 %0, t; }" : "=r"(a) : "l"(p));
    return a;
}

#define CP_ASYNC16(s, g, sz) \
    asm volatile("cp.async.cg.shared.global [%0], [%1], 16, %2;" :: "r"(s), "l"(g), "r"(sz))
#define CP_COMMIT()  asm volatile("cp.async.commit_group;")
#define CP_WAIT0()   asm volatile("cp.async.wait_group 0;")
#define CP_WAIT1()   asm volatile("cp.async.wait_group 1;")

#define LDSM4(r, addr) \
    asm volatile("ldmatrix.sync.aligned.m8n8.x4.shared.b16 {%0,%1,%2,%3}, [%4];" \
        : "=r"((r)[0]), "=r"((r)[1]), "=r"((r)[2]), "=r"((r)[3]) : "r"(addr))

#define MMA16816(d, a, b0, b1) \
    asm volatile("mma.sync.aligned.m16n8k16.row.col.f32.f16.f16.f32 " \
        "{%0,%1,%2,%3}, {%4,%5,%6,%7}, {%8,%9}, {%0,%1,%2,%3};" \
        : "+f"((d)[0]), "+f"((d)[1]), "+f"((d)[2]), "+f"((d)[3]) \
        : "r"((a)[0]), "r"((a)[1]), "r"((a)[2]), "r"((a)[3]), "r"(b0), "r"(b1))

// swizzled 16B-chunk offset within a [row][64B] tile
__device__ __forceinline__ uint32_t swz_off(int row, int chunk) {
    return (uint32_t)(row * 64 + ((chunk ^ ((row >> 1) & 3)) << 4));
}

// ---------------------------------------------------------------------------
// fused prep: comb build + w1 + w2 fp32->fp16, 4-wide
// ---------------------------------------------------------------------------
#define COMB4 (M_COMB * KDIM / 4)
#define W14   (QKV_N * KDIM / 4)
#define W24   (D_MODEL * KDIM / 4)

__global__ void prep_kernel(const float* __restrict__ mn,
                            const float* __restrict__ bg,
                            const float* __restrict__ ed,
                            const float* __restrict__ w1,
                            const float* __restrict__ w2)
{
    int i = blockIdx.x * blockDim.x + threadIdx.x;
    const float4* src;
    __half* dst;
    if (i < COMB4) {
        int row = i / (KDIM/4), c4 = i % (KDIM/4);
        if (row < OVERLAP)                src = (const float4*)(bg + (size_t)row * KDIM) + c4;
        else if (row < OVERLAP + N_LINES) src = (const float4*)(mn + (size_t)(row - OVERLAP) * KDIM) + c4;
        else                              src = (const float4*)(ed + (size_t)(row - OVERLAP - N_LINES) * KDIM) + c4;
        dst = g_comb + (size_t)i * 4;
    } else if (i < COMB4 + W14) {
        int j = i - COMB4;
        src = (const float4*)w1 + j;
        dst = g_w1 + (size_t)j * 4;
    } else if (i < COMB4 + W14 + W24) {
        int j = i - COMB4 - W14;
        src = (const float4*)w2 + j;
        dst = g_w2 + (size_t)j * 4;
    } else return;
    float4 v = *src;
    __half2* d2 = (__half2*)dst;
    d2[0] = __floats2half2_rn(v.x, v.y);
    d2[1] = __floats2half2_rn(v.z, v.w);
}

__global__ void copy_main(const float* __restrict__ mn, float* __restrict__ out)
{
    int i = blockIdx.x * blockDim.x + threadIdx.x;
    const int total = N_LINES * D_MODEL / 4;
    if (i >= total) return;
    int row = i / (D_MODEL/4), c4 = i % (D_MODEL/4);
    ((float4*)(out + (size_t)row * 2 * D_MODEL))[c4] =
        ((const float4*)(mn + (size_t)row * D_MODEL))[c4];
}

// ---------------------------------------------------------------------------
// HMMA GEMM fp16: C[m, coff+n] = sum_k A[m,k]*W[n,k] + bias[n]
// BM=128, BN=256, BK=32, 256 threads (8 warps 2x4), warp tile 64x64.
// 3-stage cp.async pipeline. Stage = A 8KB + B 16KB = 24KB.
// ---------------------------------------------------------------------------
#define STAGE_BYTES 24576
#define NSTAGE      3
#define GEMM_SMEM   (NSTAGE * STAGE_BYTES)

__device__ __forceinline__ void load_stage(uint32_t smb, int stage,
                                           const __half* A, const __half* B,
                                           int bm, int bn, int k0, int M, int tid)
{
    const uint32_t base = smb + stage * STAGE_BYTES;
    // A: 128 rows x 4 chunks = 512 ops
    #pragma unroll
    for (int i = 0; i < 2; i++) {
        int idx = tid + i * 256;
        int row = idx >> 2, c = idx & 3;
        int m = bm + row;
        int msz = (m < M) ? 16 : 0;
        int mc = (m < M) ? m : (M - 1);
        const char* ga = (const char*)(A + (size_t)mc * KDIM + k0 + c * 8);
        CP_ASYNC16(base + swz_off(row, c), ga, msz);
    }
    // B: 256 rows x 4 chunks = 1024 ops
    #pragma unroll
    for (int i = 0; i < 4; i++) {
        int idx = tid + i * 256;
        int row = idx >> 2, c = idx & 3;
        int n = bn + row;
        const char* gb = (const char*)(B + (size_t)n * KDIM + k0 + c * 8);
        CP_ASYNC16(base + 8192 + swz_off(row, c), gb, 16);
    }
}

template <bool HALF_OUT>
__global__ __launch_bounds__(256, 1)
void gemm_fp16(int M,
               const __half* __restrict__ A, const __half* __restrict__ B,
               const float* __restrict__ bias,
               void* __restrict__ Cv, int ldc, int coff)
{
    extern __shared__ char sm[];
    const uint32_t smb = smem_u32(sm);
    const int tid  = threadIdx.x;
    const int lane = tid & 31;
    const int wid  = tid >> 5;
    const int wm   = wid & 1;        // 2 warps over M (64 rows each)
    const int wn   = wid >> 1;       // 4 warps over N (64 cols each)
    const int bm = blockIdx.y * 128;
    const int bn = blockIdx.x * 256;

    float acc[4][8][4];
    #pragma unroll
    for (int i = 0; i < 4; i++)
        #pragma unroll
        for (int j = 0; j < 8; j++)
            #pragma unroll
            for (int r = 0; r < 4; r++) acc[i][j][r] = 0.f;

    load_stage(smb, 0, A, B, bm, bn, 0, M, tid);
    CP_COMMIT();
    load_stage(smb, 1, A, B, bm, bn, BK, M, tid);
    CP_COMMIT();

    const int lane15 = lane & 15;
    const int aChunkSel = lane >> 4;
    const int bRow = ((lane & 16) >> 1) + (lane & 7);
    const int bChunkSel = (lane >> 3) & 1;

    int stage = 0;
    for (int c = 0; c < CHUNKS; c++) {
        if (c == CHUNKS - 1) { CP_WAIT0(); } else { CP_WAIT1(); }
        __syncthreads();
        if (c + 2 < CHUNKS) {
            int ns = stage + 2; if (ns >= NSTAGE) ns -= NSTAGE;
            load_stage(smb, ns, A, B, bm, bn, (c + 2) * BK, M, tid);
            CP_COMMIT();
        }
        const uint32_t base = smb + stage * STAGE_BYTES;

        #pragma unroll
        for (int ks = 0; ks < 2; ks++) {
            const int c0 = ks * 2;
            uint32_t af[4][4], bf[4][4];
            #pragma unroll
            for (int mt = 0; mt < 4; mt++) {
                int row = wm * 64 + mt * 16 + lane15;
                LDSM4(af[mt], base + swz_off(row, c0 + aChunkSel));
            }
            #pragma unroll
            for (int bt = 0; bt < 4; bt++) {
                int row = wn * 64 + bt * 16 + bRow;
                LDSM4(bf[bt], base + 8192 + swz_off(row, c0 + bChunkSel));
            }
            #pragma unroll
            for (int mt = 0; mt < 4; mt++)
                #pragma unroll
                for (int nt = 0; nt < 8; nt++) {
                    const uint32_t* bp = bf[nt >> 1] + ((nt & 1) << 1);
                    MMA16816(acc[mt][nt], af[mt], bp[0], bp[1]);
                }
        }
        stage++; if (stage >= NSTAGE) stage = 0;
    }

    // epilogue
    #pragma unroll
    for (int mt = 0; mt < 4; mt++) {
        int m0 = bm + wm * 64 + mt * 16 + (lane >> 2);
        #pragma unroll
        for (int nt = 0; nt < 8; nt++) {
            int n = bn + wn * 64 + nt * 8 + (lane & 3) * 2;
            float bx = bias[n], by = bias[n + 1];
            if (HALF_OUT) {
                __half* C = (__half*)Cv;
                if (m0 < M) {
                    __half2 v = __floats2half2_rn(acc[mt][nt][0] + bx, acc[mt][nt][1] + by);
                    *(__half2*)(C + (size_t)m0 * ldc + coff + n) = v;
                }
                if (m0 + 8 < M) {
                    __half2 v = __floats2half2_rn(acc[mt][nt][2] + bx, acc[mt][nt][3] + by);
                    *(__half2*)(C + (size_t)(m0 + 8) * ldc + coff + n) = v;
                }
            } else {
                float* C = (float*)Cv;
                if (m0 < M) {
                    float2 v = make_float2(acc[mt][nt][0] + bx, acc[mt][nt][1] + by);
                    *(float2*)(C + (size_t)m0 * ldc + coff + n) = v;
                }
                if (m0 + 8 < M) {
                    float2 v = make_float2(acc[mt][nt][2] + bx, acc[mt][nt][3] + by);
                    *(float2*)(C + (size_t)(m0 + 8) * ldc + coff + n) = v;
                }
            }
        }
    }
}

// ---------------------------------------------------------------------------
// Attention: one block per line, one warp per head. fp16 P in, fp16 ctx out.
// ---------------------------------------------------------------------------
__global__ __launch_bounds__(256)
void attn_kernel(const __half* __restrict__ P, __half* __restrict__ ctx)
{
    int n = blockIdx.x;
    int h = threadIdx.x >> 5;
    int lane = threadIdx.x & 31;

    const float scale = rsqrtf((float)HD);
    const __half* qrow = P + (size_t)(n + OVERLAP) * QKV_N + h * HD;
    float q0 = __half2float(qrow[lane])      * scale;
    float q1 = __half2float(qrow[lane + 32]) * scale;
    float q2 = __half2float(qrow[lane + 64]) * scale;

    float s[W_KEYS];
    #pragma unroll
    for (int w = 0; w < W_KEYS; w++) {
        int off = (w < 8) ? (-OVERLAP + GAP * w) : (GAP * (w - 7));
        const __half* krow = P + (size_t)(n + OVERLAP + off) * QKV_N + D_MODEL + h * HD;
        float p = q0 * __half2float(krow[lane])
                + q1 * __half2float(krow[lane + 32])
                + q2 * __half2float(krow[lane + 64]);
        #pragma unroll
        for (int d = 16; d > 0; d >>= 1) p += __shfl_xor_sync(0xffffffffu, p, d);
        s[w] = p;
    }
    float m = s[0];
    #pragma unroll
    for (int w = 1; w < W_KEYS; w++) m = fmaxf(m, s[w]);
    float sum = 0.f;
    #pragma unroll
    for (int w = 0; w < W_KEYS; w++) { s[w] = expf(s[w] - m); sum += s[w]; }
    float inv = 1.f / sum;

    float a0 = 0.f, a1 = 0.f, a2 = 0.f;
    #pragma unroll
    for (int w = 0; w < W_KEYS; w++) {
        int off = (w < 8) ? (-OVERLAP + GAP * w) : (GAP * (w - 7));
        const __half* vrow = P + (size_t)(n + OVERLAP + off) * QKV_N + 2*D_MODEL + h * HD;
        float p = s[w] * inv;
        a0 = fmaf(p, __half2float(vrow[lane]),      a0);
        a1 = fmaf(p, __half2float(vrow[lane + 32]), a1);
        a2 = fmaf(p, __half2float(vrow[lane + 64]), a2);
    }

    size_t o = (size_t)n * D_MODEL + h * HD;
    ctx[o + lane]      = __float2half_rn(a0);
    ctx[o + lane + 32] = __float2half_rn(a1);
    ctx[o + lane + 64] = __float2half_rn(a2);
}

// ---------------------------------------------------------------------------
extern "C" void kernel_launch(void* const* d_in, const int* in_sizes, int n_in,
                              void* d_out, int out_size)
{
    const float* mn   = (const float*)d_in[0];
    const float* bg   = (const float*)d_in[1];
    const float* ed   = (const float*)d_in[2];
    const float* wqkv = (const float*)d_in[3];
    const float* bqkv = (const float*)d_in[4];
    const float* wo   = (const float*)d_in[5];
    const float* bo   = (const float*)d_in[6];
    float* out = (float*)d_out;

    void *pP, *pc, *pw1, *pw2, *pcx;
    cudaGetSymbolAddress(&pP,  g_P);
    cudaGetSymbolAddress(&pc,  g_comb);
    cudaGetSymbolAddress(&pw1, g_w1);
    cudaGetSymbolAddress(&pw2, g_w2);
    cudaGetSymbolAddress(&pcx, g_ctx);

    cudaFuncSetAttribute(gemm_fp16<true>,  cudaFuncAttributeMaxDynamicSharedMemorySize, GEMM_SMEM);
    cudaFuncSetAttribute(gemm_fp16<false>, cudaFuncAttributeMaxDynamicSharedMemorySize, GEMM_SMEM);

    // prep (fused) + main copy
    {
        int total4 = COMB4 + W14 + W24;
        prep_kernel<<<(total4 + 255) / 256, 256>>>(mn, bg, ed, wqkv, wo);
        int t4 = N_LINES * D_MODEL / 4;
        copy_main<<<(t4 + 255) / 256, 256>>>(mn, out);
    }
    // GEMM1: P = comb @ wqkv^T + bqkv  (M=8256, N=2304) -> fp16 P
    {
        dim3 grid(QKV_N / 256, (M_COMB + 127) / 128);
        gemm_fp16<true><<<grid, 256, GEMM_SMEM>>>(M_COMB,
            (const __half*)pc, (const __half*)pw1, bqkv, pP, QKV_N, 0);
    }
    // attention -> ctx (fp16)
    attn_kernel<<<N_LINES, 256>>>((const __half*)pP, (__half*)pcx);

    // GEMM2: out[:,768:] = ctx @ wo^T + bo  (M=8192, N=768) -> fp32 out
    {
        dim3 grid(D_MODEL / 256, N_LINES / 128);
        gemm_fp16<false><<<grid, 256, GEMM_SMEM>>>(N_LINES,
            (const __half*)pcx, (const __half*)pw2, bo, out, 2 * D_MODEL, D_MODEL);
    }
}

// round 6
// speedup vs baseline: 5.3490x; 1.1290x over previous
#include <cuda_runtime.h>
#include <cuda_fp16.h>
#include <cstdint>

#define N_LINES   8192
#define D_MODEL   768
#define HD        96
#define OVERLAP   32
#define GAP       4
#define W_KEYS    16
#define M_COMB    (N_LINES + 2*OVERLAP)   // 8256
#define QKV_N     (3*D_MODEL)             // 2304
#define KDIM      768
#define BK        32
#define CHUNKS    (KDIM / BK)             // 24

// ---- scratch (device globals) ----
__device__ __half g_comb[(size_t)M_COMB * KDIM];
__device__ __half g_P[(size_t)M_COMB * QKV_N];
__device__ __half g_w1[(size_t)QKV_N * KDIM];
__device__ __half g_w2[(size_t)D_MODEL * KDIM];
__device__ __half g_ctx[(size_t)N_LINES * KDIM];

// ---------------- PTX helpers ----------------
__device__ __forceinline__ uint32_t smem_u32(const void* p) {
    uint32_t a;
    asm("{ .reg .u64 t; cvta.to.shared.u64 t, %1; cvt.u32.u64 %0, t; }" : "=r"(a) : "l"(p));
    return a;
}

#define CP_ASYNC16(s, g, sz) \
    asm volatile("cp.async.cg.shared.global [%0], [%1], 16, %2;" :: "r"(s), "l"(g), "r"(sz))
#define CP_COMMIT()  asm volatile("cp.async.commit_group;")
#define CP_WAIT0()   asm volatile("cp.async.wait_group 0;")
#define CP_WAIT1()   asm volatile("cp.async.wait_group 1;")

#define LDSM4(r, addr) \
    asm volatile("ldmatrix.sync.aligned.m8n8.x4.shared.b16 {%0,%1,%2,%3}, [%4];" \
        : "=r"((r)[0]), "=r"((r)[1]), "=r"((r)[2]), "=r"((r)[3]) : "r"(addr))

#define MMA16816(d, a, b0, b1) \
    asm volatile("mma.sync.aligned.m16n8k16.row.col.f32.f16.f16.f32 " \
        "{%0,%1,%2,%3}, {%4,%5,%6,%7}, {%8,%9}, {%0,%1,%2,%3};" \
        : "+f"((d)[0]), "+f"((d)[1]), "+f"((d)[2]), "+f"((d)[3]) \
        : "r"((a)[0]), "r"((a)[1]), "r"((a)[2]), "r"((a)[3]), "r"(b0), "r"(b1))

__device__ __forceinline__ uint32_t swz_off(int row, int chunk) {
    return (uint32_t)(row * 64 + ((chunk ^ ((row >> 1) & 3)) << 4));
}

// ---------------------------------------------------------------------------
// fused prep: comb build + w1 + w2 fp32->fp16, 4-wide
// ---------------------------------------------------------------------------
#define COMB4 (M_COMB * KDIM / 4)
#define W14   (QKV_N * KDIM / 4)
#define W24   (D_MODEL * KDIM / 4)

__global__ void prep_kernel(const float* __restrict__ mn,
                            const float* __restrict__ bg,
                            const float* __restrict__ ed,
                            const float* __restrict__ w1,
                            const float* __restrict__ w2)
{
    int i = blockIdx.x * blockDim.x + threadIdx.x;
    const float4* src;
    __half* dst;
    if (i < COMB4) {
        int row = i / (KDIM/4), c4 = i % (KDIM/4);
        if (row < OVERLAP)                src = (const float4*)(bg + (size_t)row * KDIM) + c4;
        else if (row < OVERLAP + N_LINES) src = (const float4*)(mn + (size_t)(row - OVERLAP) * KDIM) + c4;
        else                              src = (const float4*)(ed + (size_t)(row - OVERLAP - N_LINES) * KDIM) + c4;
        dst = g_comb + (size_t)i * 4;
    } else if (i < COMB4 + W14) {
        int j = i - COMB4;
        src = (const float4*)w1 + j;
        dst = g_w1 + (size_t)j * 4;
    } else if (i < COMB4 + W14 + W24) {
        int j = i - COMB4 - W14;
        src = (const float4*)w2 + j;
        dst = g_w2 + (size_t)j * 4;
    } else return;
    float4 v = *src;
    __half2* d2 = (__half2*)dst;
    d2[0] = __floats2half2_rn(v.x, v.y);
    d2[1] = __floats2half2_rn(v.z, v.w);
}

__global__ void copy_main(const float* __restrict__ mn, float* __restrict__ out)
{
    int i = blockIdx.x * blockDim.x + threadIdx.x;
    const int total = N_LINES * D_MODEL / 4;
    if (i >= total) return;
    int row = i / (D_MODEL/4), c4 = i % (D_MODEL/4);
    ((float4*)(out + (size_t)row * 2 * D_MODEL))[c4] =
        ((const float4*)(mn + (size_t)row * D_MODEL))[c4];
}

// ---------------------------------------------------------------------------
// HMMA GEMM fp16: BM=128, BN=256, BK=32, 8 warps (2x4), warp tile 64x64,
// 3-stage cp.async pipeline.
// ---------------------------------------------------------------------------
#define STAGE_BYTES 24576
#define NSTAGE      3
#define GEMM_SMEM   (NSTAGE * STAGE_BYTES)

__device__ __forceinline__ void load_stage(uint32_t smb, int stage,
                                           const __half* A, const __half* B,
                                           int bm, int bn, int k0, int M, int tid)
{
    const uint32_t base = smb + stage * STAGE_BYTES;
    #pragma unroll
    for (int i = 0; i < 2; i++) {
        int idx = tid + i * 256;
        int row = idx >> 2, c = idx & 3;
        int m = bm + row;
        int msz = (m < M) ? 16 : 0;
        int mc = (m < M) ? m : (M - 1);
        const char* ga = (const char*)(A + (size_t)mc * KDIM + k0 + c * 8);
        CP_ASYNC16(base + swz_off(row, c), ga, msz);
    }
    #pragma unroll
    for (int i = 0; i < 4; i++) {
        int idx = tid + i * 256;
        int row = idx >> 2, c = idx & 3;
        int n = bn + row;
        const char* gb = (const char*)(B + (size_t)n * KDIM + k0 + c * 8);
        CP_ASYNC16(base + 8192 + swz_off(row, c), gb, 16);
    }
}

template <bool HALF_OUT>
__global__ __launch_bounds__(256, 1)
void gemm_fp16(int M,
               const __half* __restrict__ A, const __half* __restrict__ B,
               const float* __restrict__ bias,
               void* __restrict__ Cv, int ldc, int coff)
{
    extern __shared__ char sm[];
    const uint32_t smb = smem_u32(sm);
    const int tid  = threadIdx.x;
    const int lane = tid & 31;
    const int wid  = tid >> 5;
    const int wm   = wid & 1;
    const int wn   = wid >> 1;
    const int bm = blockIdx.y * 128;
    const int bn = blockIdx.x * 256;

    float acc[4][8][4];
    #pragma unroll
    for (int i = 0; i < 4; i++)
        #pragma unroll
        for (int j = 0; j < 8; j++)
            #pragma unroll
            for (int r = 0; r < 4; r++) acc[i][j][r] = 0.f;

    load_stage(smb, 0, A, B, bm, bn, 0, M, tid);
    CP_COMMIT();
    load_stage(smb, 1, A, B, bm, bn, BK, M, tid);
    CP_COMMIT();

    const int lane15 = lane & 15;
    const int aChunkSel = lane >> 4;
    const int bRow = ((lane & 16) >> 1) + (lane & 7);
    const int bChunkSel = (lane >> 3) & 1;

    int stage = 0;
    for (int c = 0; c < CHUNKS; c++) {
        if (c == CHUNKS - 1) { CP_WAIT0(); } else { CP_WAIT1(); }
        __syncthreads();
        if (c + 2 < CHUNKS) {
            int ns = stage + 2; if (ns >= NSTAGE) ns -= NSTAGE;
            load_stage(smb, ns, A, B, bm, bn, (c + 2) * BK, M, tid);
            CP_COMMIT();
        }
        const uint32_t base = smb + stage * STAGE_BYTES;

        #pragma unroll
        for (int ks = 0; ks < 2; ks++) {
            const int c0 = ks * 2;
            uint32_t af[4][4], bf[4][4];
            #pragma unroll
            for (int mt = 0; mt < 4; mt++) {
                int row = wm * 64 + mt * 16 + lane15;
                LDSM4(af[mt], base + swz_off(row, c0 + aChunkSel));
            }
            #pragma unroll
            for (int bt = 0; bt < 4; bt++) {
                int row = wn * 64 + bt * 16 + bRow;
                LDSM4(bf[bt], base + 8192 + swz_off(row, c0 + bChunkSel));
            }
            #pragma unroll
            for (int mt = 0; mt < 4; mt++)
                #pragma unroll
                for (int nt = 0; nt < 8; nt++) {
                    const uint32_t* bp = bf[nt >> 1] + ((nt & 1) << 1);
                    MMA16816(acc[mt][nt], af[mt], bp[0], bp[1]);
                }
        }
        stage++; if (stage >= NSTAGE) stage = 0;
    }

    #pragma unroll
    for (int mt = 0; mt < 4; mt++) {
        int m0 = bm + wm * 64 + mt * 16 + (lane >> 2);
        #pragma unroll
        for (int nt = 0; nt < 8; nt++) {
            int n = bn + wn * 64 + nt * 8 + (lane & 3) * 2;
            float bx = bias[n], by = bias[n + 1];
            if (HALF_OUT) {
                __half* C = (__half*)Cv;
                if (m0 < M) {
                    __half2 v = __floats2half2_rn(acc[mt][nt][0] + bx, acc[mt][nt][1] + by);
                    *(__half2*)(C + (size_t)m0 * ldc + coff + n) = v;
                }
                if (m0 + 8 < M) {
                    __half2 v = __floats2half2_rn(acc[mt][nt][2] + bx, acc[mt][nt][3] + by);
                    *(__half2*)(C + (size_t)(m0 + 8) * ldc + coff + n) = v;
                }
            } else {
                float* C = (float*)Cv;
                if (m0 < M) {
                    float2 v = make_float2(acc[mt][nt][0] + bx, acc[mt][nt][1] + by);
                    *(float2*)(C + (size_t)m0 * ldc + coff + n) = v;
                }
                if (m0 + 8 < M) {
                    float2 v = make_float2(acc[mt][nt][2] + bx, acc[mt][nt][3] + by);
                    *(float2*)(C + (size_t)(m0 + 8) * ldc + coff + n) = v;
                }
            }
        }
    }
}

// ---------------------------------------------------------------------------
// Attention v2: one WARP per line; 4 lanes per head (8 heads x 4 lanes).
// Each lane owns 24 contiguous dims (3x uint4 = 48B). Score reduce = 2 shfls.
// ---------------------------------------------------------------------------
__global__ __launch_bounds__(256)
void attn_kernel(const __half* __restrict__ P, __half* __restrict__ ctx)
{
    const int warp = threadIdx.x >> 5;
    const int lane = threadIdx.x & 31;
    const int n = blockIdx.x * 8 + warp;
    const int dimoff = lane * 24;            // 0..744, lane's 24 dims within 768

    const float scale = rsqrtf((float)HD);

    // load q (24 halves = 3 uint4), convert to float, pre-scale
    float qf[24];
    {
        const uint4* qp = (const uint4*)(P + (size_t)(n + OVERLAP) * QKV_N + dimoff);
        #pragma unroll
        for (int t = 0; t < 3; t++) {
            uint4 u = qp[t];
            const __half2* h2 = (const __half2*)&u;
            #pragma unroll
            for (int j = 0; j < 4; j++) {
                float2 f = __half22float2(h2[j]);
                qf[t*8 + 2*j]     = f.x * scale;
                qf[t*8 + 2*j + 1] = f.y * scale;
            }
        }
    }

    // scores
    float s[W_KEYS];
    #pragma unroll
    for (int w = 0; w < W_KEYS; w++) {
        int off = (w < 8) ? (-OVERLAP + GAP * w) : (GAP * (w - 7));
        const uint4* kp = (const uint4*)(P + (size_t)(n + OVERLAP + off) * QKV_N + D_MODEL + dimoff);
        float p = 0.f;
        #pragma unroll
        for (int t = 0; t < 3; t++) {
            uint4 u = kp[t];
            const __half2* h2 = (const __half2*)&u;
            #pragma unroll
            for (int j = 0; j < 4; j++) {
                float2 f = __half22float2(h2[j]);
                p = fmaf(qf[t*8 + 2*j],     f.x, p);
                p = fmaf(qf[t*8 + 2*j + 1], f.y, p);
            }
        }
        // reduce within the 4 lanes of this head
        p += __shfl_xor_sync(0xffffffffu, p, 1);
        p += __shfl_xor_sync(0xffffffffu, p, 2);
        s[w] = p;
    }

    // softmax (lane-local; replicated across the 4 lanes of a head)
    float m = s[0];
    #pragma unroll
    for (int w = 1; w < W_KEYS; w++) m = fmaxf(m, s[w]);
    float sum = 0.f;
    #pragma unroll
    for (int w = 0; w < W_KEYS; w++) { s[w] = __expf(s[w] - m); sum += s[w]; }
    float inv = 1.f / sum;

    // V accumulation
    float c[24];
    #pragma unroll
    for (int j = 0; j < 24; j++) c[j] = 0.f;
    #pragma unroll
    for (int w = 0; w < W_KEYS; w++) {
        int off = (w < 8) ? (-OVERLAP + GAP * w) : (GAP * (w - 7));
        const uint4* vp = (const uint4*)(P + (size_t)(n + OVERLAP + off) * QKV_N + 2*D_MODEL + dimoff);
        float p = s[w] * inv;
        #pragma unroll
        for (int t = 0; t < 3; t++) {
            uint4 u = vp[t];
            const __half2* h2 = (const __half2*)&u;
            #pragma unroll
            for (int j = 0; j < 4; j++) {
                float2 f = __half22float2(h2[j]);
                c[t*8 + 2*j]     = fmaf(p, f.x, c[t*8 + 2*j]);
                c[t*8 + 2*j + 1] = fmaf(p, f.y, c[t*8 + 2*j + 1]);
            }
        }
    }

    // store ctx (24 halves = 3 uint4)
    uint4* cp = (uint4*)(ctx + (size_t)n * D_MODEL + dimoff);
    #pragma unroll
    for (int t = 0; t < 3; t++) {
        uint4 u;
        __half2* h2 = (__half2*)&u;
        #pragma unroll
        for (int j = 0; j < 4; j++)
            h2[j] = __floats2half2_rn(c[t*8 + 2*j], c[t*8 + 2*j + 1]);
        cp[t] = u;
    }
}

// ---------------------------------------------------------------------------
extern "C" void kernel_launch(void* const* d_in, const int* in_sizes, int n_in,
                              void* d_out, int out_size)
{
    const float* mn   = (const float*)d_in[0];
    const float* bg   = (const float*)d_in[1];
    const float* ed   = (const float*)d_in[2];
    const float* wqkv = (const float*)d_in[3];
    const float* bqkv = (const float*)d_in[4];
    const float* wo   = (const float*)d_in[5];
    const float* bo   = (const float*)d_in[6];
    float* out = (float*)d_out;

    void *pP, *pc, *pw1, *pw2, *pcx;
    cudaGetSymbolAddress(&pP,  g_P);
    cudaGetSymbolAddress(&pc,  g_comb);
    cudaGetSymbolAddress(&pw1, g_w1);
    cudaGetSymbolAddress(&pw2, g_w2);
    cudaGetSymbolAddress(&pcx, g_ctx);

    cudaFuncSetAttribute(gemm_fp16<true>,  cudaFuncAttributeMaxDynamicSharedMemorySize, GEMM_SMEM);
    cudaFuncSetAttribute(gemm_fp16<false>, cudaFuncAttributeMaxDynamicSharedMemorySize, GEMM_SMEM);

    // prep (fused) + main copy
    {
        int total4 = COMB4 + W14 + W24;
        prep_kernel<<<(total4 + 255) / 256, 256>>>(mn, bg, ed, wqkv, wo);
        int t4 = N_LINES * D_MODEL / 4;
        copy_main<<<(t4 + 255) / 256, 256>>>(mn, out);
    }
    // GEMM1: P = comb @ wqkv^T + bqkv  (M=8256, N=2304) -> fp16 P
    {
        dim3 grid(QKV_N / 256, (M_COMB + 127) / 128);
        gemm_fp16<true><<<grid, 256, GEMM_SMEM>>>(M_COMB,
            (const __half*)pc, (const __half*)pw1, bqkv, pP, QKV_N, 0);
    }
    // attention -> ctx (fp16), one warp per line
    attn_kernel<<<N_LINES / 8, 256>>>((const __half*)pP, (__half*)pcx);

    // GEMM2: out[:,768:] = ctx @ wo^T + bo  (M=8192, N=768) -> fp32 out
    {
        dim3 grid(D_MODEL / 256, N_LINES / 128);
        gemm_fp16<false><<<grid, 256, GEMM_SMEM>>>(N_LINES,
            (const __half*)pcx, (const __half*)pw2, bo, out, 2 * D_MODEL, D_MODEL);
    }
}

// round 7
// speedup vs baseline: 6.0476x; 1.1306x over previous
#include <cuda_runtime.h>
#include <cuda_fp16.h>
#include <cstdint>

#define N_LINES   8192
#define D_MODEL   768
#define HD        96
#define OVERLAP   32
#define GAP       4
#define W_KEYS    16
#define M_COMB    (N_LINES + 2*OVERLAP)   // 8256
#define M_PAD     8320                    // 65*128
#define QKV_N     (3*D_MODEL)             // 2304
#define KDIM      768
#define BK        32
#define CHUNKS    (KDIM / BK)             // 24

// ---- scratch (device globals, padded M) ----
__device__ __half g_comb[(size_t)M_PAD * KDIM];
__device__ __half g_P[(size_t)M_PAD * QKV_N];
__device__ __half g_w1[(size_t)QKV_N * KDIM];
__device__ __half g_w2[(size_t)D_MODEL * KDIM];
__device__ __half g_ctx[(size_t)N_LINES * KDIM];

// ---------------- PTX helpers ----------------
__device__ __forceinline__ uint32_t smem_u32(const void* p) {
    uint32_t a;
    asm("{ .reg .u64 t; cvta.to.shared.u64 t, %1; cvt.u32.u64 %0, t; }" : "=r"(a) : "l"(p));
    return a;
}

#define CP_ASYNC16(s, g) \
    asm volatile("cp.async.cg.shared.global [%0], [%1], 16;" :: "r"(s), "l"(g))
#define CP_COMMIT()  asm volatile("cp.async.commit_group;")
#define CP_WAIT0()   asm volatile("cp.async.wait_group 0;")
#define CP_WAIT1()   asm volatile("cp.async.wait_group 1;")

#define LDSM4(r, addr) \
    asm volatile("ldmatrix.sync.aligned.m8n8.x4.shared.b16 {%0,%1,%2,%3}, [%4];" \
        : "=r"((r)[0]), "=r"((r)[1]), "=r"((r)[2]), "=r"((r)[3]) : "r"(addr))

#define MMA16816(d, a, b0, b1) \
    asm volatile("mma.sync.aligned.m16n8k16.row.col.f32.f16.f16.f32 " \
        "{%0,%1,%2,%3}, {%4,%5,%6,%7}, {%8,%9}, {%0,%1,%2,%3};" \
        : "+f"((d)[0]), "+f"((d)[1]), "+f"((d)[2]), "+f"((d)[3]) \
        : "r"((a)[0]), "r"((a)[1]), "r"((a)[2]), "r"((a)[3]), "r"(b0), "r"(b1))

__device__ __forceinline__ uint32_t swz_off(int row, int chunk) {
    return (uint32_t)(row * 64 + ((chunk ^ ((row >> 1) & 3)) << 4));
}

// ---------------------------------------------------------------------------
// fused prep: comb build + w1 + w2 fp32->fp16, 4-wide
// ---------------------------------------------------------------------------
#define COMB4 (M_COMB * KDIM / 4)
#define W14   (QKV_N * KDIM / 4)
#define W24   (D_MODEL * KDIM / 4)

__global__ void prep_kernel(const float* __restrict__ mn,
                            const float* __restrict__ bg,
                            const float* __restrict__ ed,
                            const float* __restrict__ w1,
                            const float* __restrict__ w2)
{
    int i = blockIdx.x * blockDim.x + threadIdx.x;
    const float4* src;
    __half* dst;
    if (i < COMB4) {
        int row = i / (KDIM/4), c4 = i % (KDIM/4);
        if (row < OVERLAP)                src = (const float4*)(bg + (size_t)row * KDIM) + c4;
        else if (row < OVERLAP + N_LINES) src = (const float4*)(mn + (size_t)(row - OVERLAP) * KDIM) + c4;
        else                              src = (const float4*)(ed + (size_t)(row - OVERLAP - N_LINES) * KDIM) + c4;
        dst = g_comb + (size_t)i * 4;
    } else if (i < COMB4 + W14) {
        int j = i - COMB4;
        src = (const float4*)w1 + j;
        dst = g_w1 + (size_t)j * 4;
    } else if (i < COMB4 + W14 + W24) {
        int j = i - COMB4 - W14;
        src = (const float4*)w2 + j;
        dst = g_w2 + (size_t)j * 4;
    } else return;
    float4 v = *src;
    __half2* d2 = (__half2*)dst;
    d2[0] = __floats2half2_rn(v.x, v.y);
    d2[1] = __floats2half2_rn(v.z, v.w);
}

// ---------------------------------------------------------------------------
// HMMA GEMM fp16: BM=128, BN=128, BK=32, 8 warps (2x4), warp tile 64x32,
// 3-stage cp.async pipeline, 2 CTAs/SM. No bounds checks (M padded).
// ---------------------------------------------------------------------------
#define STAGE_BYTES 16384
#define NSTAGE      3
#define GEMM_SMEM   (NSTAGE * STAGE_BYTES)

__device__ __forceinline__ void load_stage(uint32_t smb, int stage,
                                           const __half* A, const __half* B,
                                           int bm, int bn, int k0, int tid)
{
    const uint32_t base = smb + stage * STAGE_BYTES;
    #pragma unroll
    for (int i = 0; i < 2; i++) {
        int idx = tid + i * 256;
        int row = idx >> 2, c = idx & 3;
        const char* ga = (const char*)(A + (size_t)(bm + row) * KDIM + k0 + c * 8);
        CP_ASYNC16(base + swz_off(row, c), ga);
        const char* gb = (const char*)(B + (size_t)(bn + row) * KDIM + k0 + c * 8);
        CP_ASYNC16(base + 8192 + swz_off(row, c), gb);
    }
}

template <bool HALF_OUT>
__global__ __launch_bounds__(256, 2)
void gemm_fp16(const __half* __restrict__ A, const __half* __restrict__ B,
               const float* __restrict__ bias,
               void* __restrict__ Cv, int ldc, int coff)
{
    extern __shared__ char sm[];
    const uint32_t smb = smem_u32(sm);
    const int tid  = threadIdx.x;
    const int lane = tid & 31;
    const int wid  = tid >> 5;
    const int wm   = wid & 1;       // 2 warps over M (64 rows)
    const int wn   = wid >> 1;      // 4 warps over N (32 cols)
    const int bm = blockIdx.y * 128;
    const int bn = blockIdx.x * 128;

    float acc[4][4][4];
    #pragma unroll
    for (int i = 0; i < 4; i++)
        #pragma unroll
        for (int j = 0; j < 4; j++)
            #pragma unroll
            for (int r = 0; r < 4; r++) acc[i][j][r] = 0.f;

    load_stage(smb, 0, A, B, bm, bn, 0, tid);
    CP_COMMIT();
    load_stage(smb, 1, A, B, bm, bn, BK, tid);
    CP_COMMIT();

    const int lane15 = lane & 15;
    const int aChunkSel = lane >> 4;
    const int bRow = ((lane & 16) >> 1) + (lane & 7);
    const int bChunkSel = (lane >> 3) & 1;

    int stage = 0;
    for (int c = 0; c < CHUNKS; c++) {
        if (c == CHUNKS - 1) { CP_WAIT0(); } else { CP_WAIT1(); }
        __syncthreads();
        if (c + 2 < CHUNKS) {
            int ns = stage + 2; if (ns >= NSTAGE) ns -= NSTAGE;
            load_stage(smb, ns, A, B, bm, bn, (c + 2) * BK, tid);
            CP_COMMIT();
        }
        const uint32_t base = smb + stage * STAGE_BYTES;

        #pragma unroll
        for (int ks = 0; ks < 2; ks++) {
            const int c0 = ks * 2;
            uint32_t af[4][4], bf[2][4];
            #pragma unroll
            for (int mt = 0; mt < 4; mt++) {
                int row = wm * 64 + mt * 16 + lane15;
                LDSM4(af[mt], base + swz_off(row, c0 + aChunkSel));
            }
            #pragma unroll
            for (int bt = 0; bt < 2; bt++) {
                int row = wn * 32 + bt * 16 + bRow;
                LDSM4(bf[bt], base + 8192 + swz_off(row, c0 + bChunkSel));
            }
            #pragma unroll
            for (int mt = 0; mt < 4; mt++)
                #pragma unroll
                for (int nt = 0; nt < 4; nt++) {
                    const uint32_t* bp = bf[nt >> 1] + ((nt & 1) << 1);
                    MMA16816(acc[mt][nt], af[mt], bp[0], bp[1]);
                }
        }
        stage++; if (stage >= NSTAGE) stage = 0;
    }

    #pragma unroll
    for (int mt = 0; mt < 4; mt++) {
        int m0 = bm + wm * 64 + mt * 16 + (lane >> 2);
        #pragma unroll
        for (int nt = 0; nt < 4; nt++) {
            int n = bn + wn * 32 + nt * 8 + (lane & 3) * 2;
            float bx = bias[n], by = bias[n + 1];
            if (HALF_OUT) {
                __half* C = (__half*)Cv;
                *(__half2*)(C + (size_t)m0 * ldc + coff + n) =
                    __floats2half2_rn(acc[mt][nt][0] + bx, acc[mt][nt][1] + by);
                *(__half2*)(C + (size_t)(m0 + 8) * ldc + coff + n) =
                    __floats2half2_rn(acc[mt][nt][2] + bx, acc[mt][nt][3] + by);
            } else {
                float* C = (float*)Cv;
                *(float2*)(C + (size_t)m0 * ldc + coff + n) =
                    make_float2(acc[mt][nt][0] + bx, acc[mt][nt][1] + by);
                *(float2*)(C + (size_t)(m0 + 8) * ldc + coff + n) =
                    make_float2(acc[mt][nt][2] + bx, acc[mt][nt][3] + by);
            }
        }
    }
}

// ---------------------------------------------------------------------------
// Attention v3: 2 warps per line (4 heads each), 8 lanes/head, 12 dims/lane.
// Fused copy of main -> out[:, :768].
// Grid: N_LINES/4 blocks of 256 (8 warps = 4 lines).
// ---------------------------------------------------------------------------
__global__ __launch_bounds__(256)
void attn_kernel(const __half* __restrict__ P, __half* __restrict__ ctx,
                 const float* __restrict__ mn, float* __restrict__ out)
{
    const int warp = threadIdx.x >> 5;
    const int lane = threadIdx.x & 31;
    const int n    = blockIdx.x * 4 + (warp >> 1);
    const int half = warp & 1;                      // head group 0-3 / 4-7
    const int dimoff = half * 384 + (lane >> 3) * HD + (lane & 7) * 12;

    const float scale = rsqrtf((float)HD);

    // q: 12 halves = 3x uint2
    float qf[12];
    {
        const uint2* qp = (const uint2*)(P + (size_t)(n + OVERLAP) * QKV_N + dimoff);
        #pragma unroll
        for (int t = 0; t < 3; t++) {
            uint2 u = qp[t];
            const __half2* h2 = (const __half2*)&u;
            #pragma unroll
            for (int j = 0; j < 2; j++) {
                float2 f = __half22float2(h2[j]);
                qf[t*4 + 2*j]     = f.x * scale;
                qf[t*4 + 2*j + 1] = f.y * scale;
            }
        }
    }

    // scores
    float s[W_KEYS];
    #pragma unroll
    for (int w = 0; w < W_KEYS; w++) {
        int off = (w < 8) ? (-OVERLAP + GAP * w) : (GAP * (w - 7));
        const uint2* kp = (const uint2*)(P + (size_t)(n + OVERLAP + off) * QKV_N + D_MODEL + dimoff);
        float p = 0.f;
        #pragma unroll
        for (int t = 0; t < 3; t++) {
            uint2 u = kp[t];
            const __half2* h2 = (const __half2*)&u;
            #pragma unroll
            for (int j = 0; j < 2; j++) {
                float2 f = __half22float2(h2[j]);
                p = fmaf(qf[t*4 + 2*j],     f.x, p);
                p = fmaf(qf[t*4 + 2*j + 1], f.y, p);
            }
        }
        p += __shfl_xor_sync(0xffffffffu, p, 1);
        p += __shfl_xor_sync(0xffffffffu, p, 2);
        p += __shfl_xor_sync(0xffffffffu, p, 4);
        s[w] = p;
    }

    // softmax (replicated within each 8-lane head group)
    float m = s[0];
    #pragma unroll
    for (int w = 1; w < W_KEYS; w++) m = fmaxf(m, s[w]);
    float sum = 0.f;
    #pragma unroll
    for (int w = 0; w < W_KEYS; w++) { s[w] = __expf(s[w] - m); sum += s[w]; }
    float inv = 1.f / sum;

    // V accumulation
    float c[12];
    #pragma unroll
    for (int j = 0; j < 12; j++) c[j] = 0.f;
    #pragma unroll
    for (int w = 0; w < W_KEYS; w++) {
        int off = (w < 8) ? (-OVERLAP + GAP * w) : (GAP * (w - 7));
        const uint2* vp = (const uint2*)(P + (size_t)(n + OVERLAP + off) * QKV_N + 2*D_MODEL + dimoff);
        float p = s[w] * inv;
        #pragma unroll
        for (int t = 0; t < 3; t++) {
            uint2 u = vp[t];
            const __half2* h2 = (const __half2*)&u;
            #pragma unroll
            for (int j = 0; j < 2; j++) {
                float2 f = __half22float2(h2[j]);
                c[t*4 + 2*j]     = fmaf(p, f.x, c[t*4 + 2*j]);
                c[t*4 + 2*j + 1] = fmaf(p, f.y, c[t*4 + 2*j + 1]);
            }
        }
    }

    // store ctx (12 halves = 3x uint2)
    uint2* cp = (uint2*)(ctx + (size_t)n * D_MODEL + dimoff);
    #pragma unroll
    for (int t = 0; t < 3; t++) {
        uint2 u;
        __half2* h2 = (__half2*)&u;
        h2[0] = __floats2half2_rn(c[t*4 + 0], c[t*4 + 1]);
        h2[1] = __floats2half2_rn(c[t*4 + 2], c[t*4 + 3]);
        cp[t] = u;
    }

    // fused copy: main -> out[:, 0:768]. 768 float4 per block, 3 per thread.
    {
        int b0 = blockIdx.x * 768 + threadIdx.x;
        #pragma unroll
        for (int i = 0; i < 3; i++) {
            int idx = b0 + i * 256;
            int row = idx / 192, c4 = idx % 192;
            ((float4*)(out + (size_t)row * 2 * D_MODEL))[c4] =
                ((const float4*)(mn + (size_t)row * D_MODEL))[c4];
        }
    }
}

// ---------------------------------------------------------------------------
extern "C" void kernel_launch(void* const* d_in, const int* in_sizes, int n_in,
                              void* d_out, int out_size)
{
    const float* mn   = (const float*)d_in[0];
    const float* bg   = (const float*)d_in[1];
    const float* ed   = (const float*)d_in[2];
    const float* wqkv = (const float*)d_in[3];
    const float* bqkv = (const float*)d_in[4];
    const float* wo   = (const float*)d_in[5];
    const float* bo   = (const float*)d_in[6];
    float* out = (float*)d_out;

    void *pP, *pc, *pw1, *pw2, *pcx;
    cudaGetSymbolAddress(&pP,  g_P);
    cudaGetSymbolAddress(&pc,  g_comb);
    cudaGetSymbolAddress(&pw1, g_w1);
    cudaGetSymbolAddress(&pw2, g_w2);
    cudaGetSymbolAddress(&pcx, g_ctx);

    cudaFuncSetAttribute(gemm_fp16<true>,  cudaFuncAttributeMaxDynamicSharedMemorySize, GEMM_SMEM);
    cudaFuncSetAttribute(gemm_fp16<false>, cudaFuncAttributeMaxDynamicSharedMemorySize, GEMM_SMEM);

    // prep (fused conversions)
    {
        int total4 = COMB4 + W14 + W24;
        prep_kernel<<<(total4 + 255) / 256, 256>>>(mn, bg, ed, wqkv, wo);
    }
    // GEMM1: P = comb @ wqkv^T + bqkv  (Mpad=8320, N=2304) -> fp16 P
    {
        dim3 grid(QKV_N / 128, M_PAD / 128);
        gemm_fp16<true><<<grid, 256, GEMM_SMEM>>>(
            (const __half*)pc, (const __half*)pw1, bqkv, pP, QKV_N, 0);
    }
    // attention (+ fused main copy) -> ctx fp16
    attn_kernel<<<N_LINES / 4, 256>>>((const __half*)pP, (__half*)pcx, mn, out);

    // GEMM2: out[:,768:] = ctx @ wo^T + bo  (M=8192, N=768) -> fp32 out
    {
        dim3 grid(D_MODEL / 128, N_LINES / 128);
        gemm_fp16<false><<<grid, 256, GEMM_SMEM>>>(
            (const __half*)pcx, (const __half*)pw2, bo, out, 2 * D_MODEL, D_MODEL);
    }
}

// round 8
// speedup vs baseline: 6.1135x; 1.0109x over previous
#include <cuda_runtime.h>
#include <cuda_fp16.h>
#include <cstdint>

#define N_LINES   8192
#define D_MODEL   768
#define HD        96
#define OVERLAP   32
#define GAP       4
#define W_KEYS    16
#define M_COMB    (N_LINES + 2*OVERLAP)   // 8256
#define M_PAD     8320                    // 65*128
#define QKV_N     (3*D_MODEL)             // 2304
#define KDIM      768
#define BK        32
#define CHUNKS    (KDIM / BK)             // 24

// ---- scratch (device globals, padded M) ----
__device__ __half g_comb[(size_t)M_PAD * KDIM];
__device__ __half g_P[(size_t)M_PAD * QKV_N];
__device__ __half g_w1[(size_t)QKV_N * KDIM];
__device__ __half g_w2[(size_t)D_MODEL * KDIM];
__device__ __half g_ctx[(size_t)N_LINES * KDIM];

// ---------------- PTX helpers ----------------
__device__ __forceinline__ uint32_t smem_u32(const void* p) {
    uint32_t a;
    asm("{ .reg .u64 t; cvta.to.shared.u64 t, %1; cvt.u32.u64 %0, t; }" : "=r"(a) : "l"(p));
    return a;
}

#define CP_ASYNC16(s, g) \
    asm volatile("cp.async.cg.shared.global [%0], [%1], 16;" :: "r"(s), "l"(g))
#define CP_COMMIT()  asm volatile("cp.async.commit_group;")
#define CP_WAIT0()   asm volatile("cp.async.wait_group 0;")
#define CP_WAIT1()   asm volatile("cp.async.wait_group 1;")

#define LDSM4(r, addr) \
    asm volatile("ldmatrix.sync.aligned.m8n8.x4.shared.b16 {%0,%1,%2,%3}, [%4];" \
        : "=r"((r)[0]), "=r"((r)[1]), "=r"((r)[2]), "=r"((r)[3]) : "r"(addr))

#define MMA16816(d, a, b0, b1) \
    asm volatile("mma.sync.aligned.m16n8k16.row.col.f32.f16.f16.f32 " \
        "{%0,%1,%2,%3}, {%4,%5,%6,%7}, {%8,%9}, {%0,%1,%2,%3};" \
        : "+f"((d)[0]), "+f"((d)[1]), "+f"((d)[2]), "+f"((d)[3]) \
        : "r"((a)[0]), "r"((a)[1]), "r"((a)[2]), "r"((a)[3]), "r"(b0), "r"(b1))

__device__ __forceinline__ uint32_t swz_off(int row, int chunk) {
    return (uint32_t)(row * 64 + ((chunk ^ ((row >> 1) & 3)) << 4));
}

// ---------------------------------------------------------------------------
// fused prep: comb build + w1 + w2 fp32->fp16, 4 float4 per thread (MLP=4)
// ---------------------------------------------------------------------------
#define COMB4 (M_COMB * KDIM / 4)
#define W14   (QKV_N * KDIM / 4)
#define W24   (D_MODEL * KDIM / 4)
#define PREP_TOTAL (COMB4 + W14 + W24)

__global__ void prep_kernel(const float* __restrict__ mn,
                            const float* __restrict__ bg,
                            const float* __restrict__ ed,
                            const float* __restrict__ w1,
                            const float* __restrict__ w2)
{
    int base = blockIdx.x * 1024 + threadIdx.x;
    float4 v[4];
    __half* dsts[4];
    #pragma unroll
    for (int t = 0; t < 4; t++) {
        int i = base + t * 256;
        const float4* src = nullptr;
        __half* dst = nullptr;
        if (i < COMB4) {
            int row = i / (KDIM/4), c4 = i % (KDIM/4);
            if (row < OVERLAP)                src = (const float4*)(bg + (size_t)row * KDIM) + c4;
            else if (row < OVERLAP + N_LINES) src = (const float4*)(mn + (size_t)(row - OVERLAP) * KDIM) + c4;
            else                              src = (const float4*)(ed + (size_t)(row - OVERLAP - N_LINES) * KDIM) + c4;
            dst = g_comb + (size_t)i * 4;
        } else if (i < COMB4 + W14) {
            int j = i - COMB4;
            src = (const float4*)w1 + j;
            dst = g_w1 + (size_t)j * 4;
        } else if (i < PREP_TOTAL) {
            int j = i - COMB4 - W14;
            src = (const float4*)w2 + j;
            dst = g_w2 + (size_t)j * 4;
        }
        dsts[t] = dst;
        if (dst) v[t] = *src;
    }
    #pragma unroll
    for (int t = 0; t < 4; t++) {
        if (dsts[t]) {
            __half2* d2 = (__half2*)dsts[t];
            d2[0] = __floats2half2_rn(v[t].x, v[t].y);
            d2[1] = __floats2half2_rn(v[t].z, v[t].w);
        }
    }
}

// ---------------------------------------------------------------------------
// GEMM1: BM=128, BN=128, BK=32, 8 warps (2x4), warp tile 64x32,
// 3-stage cp.async, 2 CTAs/SM, no predicates (M padded). fp16 out.
// ---------------------------------------------------------------------------
#define STAGE1_BYTES 16384
#define NSTAGE       3
#define GEMM1_SMEM   (NSTAGE * STAGE1_BYTES)

__device__ __forceinline__ void load_stage1(uint32_t smb, int stage,
                                            const __half* A, const __half* B,
                                            int bm, int bn, int k0, int tid)
{
    const uint32_t base = smb + stage * STAGE1_BYTES;
    #pragma unroll
    for (int i = 0; i < 2; i++) {
        int idx = tid + i * 256;
        int row = idx >> 2, c = idx & 3;
        const char* ga = (const char*)(A + (size_t)(bm + row) * KDIM + k0 + c * 8);
        CP_ASYNC16(base + swz_off(row, c), ga);
        const char* gb = (const char*)(B + (size_t)(bn + row) * KDIM + k0 + c * 8);
        CP_ASYNC16(base + 8192 + swz_off(row, c), gb);
    }
}

__global__ __launch_bounds__(256, 2)
void gemm1_fp16(const __half* __restrict__ A, const __half* __restrict__ B,
                const float* __restrict__ bias, __half* __restrict__ C)
{
    extern __shared__ char sm[];
    const uint32_t smb = smem_u32(sm);
    const int tid  = threadIdx.x;
    const int lane = tid & 31;
    const int wid  = tid >> 5;
    const int wm   = wid & 1;
    const int wn   = wid >> 1;
    const int bm = blockIdx.y * 128;
    const int bn = blockIdx.x * 128;

    float acc[4][4][4];
    #pragma unroll
    for (int i = 0; i < 4; i++)
        #pragma unroll
        for (int j = 0; j < 4; j++)
            #pragma unroll
            for (int r = 0; r < 4; r++) acc[i][j][r] = 0.f;

    load_stage1(smb, 0, A, B, bm, bn, 0, tid);
    CP_COMMIT();
    load_stage1(smb, 1, A, B, bm, bn, BK, tid);
    CP_COMMIT();

    const int lane15 = lane & 15;
    const int aChunkSel = lane >> 4;
    const int bRow = ((lane & 16) >> 1) + (lane & 7);
    const int bChunkSel = (lane >> 3) & 1;

    int stage = 0;
    for (int c = 0; c < CHUNKS; c++) {
        if (c == CHUNKS - 1) { CP_WAIT0(); } else { CP_WAIT1(); }
        __syncthreads();
        if (c + 2 < CHUNKS) {
            int ns = stage + 2; if (ns >= NSTAGE) ns -= NSTAGE;
            load_stage1(smb, ns, A, B, bm, bn, (c + 2) * BK, tid);
            CP_COMMIT();
        }
        const uint32_t base = smb + stage * STAGE1_BYTES;

        #pragma unroll
        for (int ks = 0; ks < 2; ks++) {
            const int c0 = ks * 2;
            uint32_t af[4][4], bf[2][4];
            #pragma unroll
            for (int mt = 0; mt < 4; mt++) {
                int row = wm * 64 + mt * 16 + lane15;
                LDSM4(af[mt], base + swz_off(row, c0 + aChunkSel));
            }
            #pragma unroll
            for (int bt = 0; bt < 2; bt++) {
                int row = wn * 32 + bt * 16 + bRow;
                LDSM4(bf[bt], base + 8192 + swz_off(row, c0 + bChunkSel));
            }
            #pragma unroll
            for (int mt = 0; mt < 4; mt++)
                #pragma unroll
                for (int nt = 0; nt < 4; nt++) {
                    const uint32_t* bp = bf[nt >> 1] + ((nt & 1) << 1);
                    MMA16816(acc[mt][nt], af[mt], bp[0], bp[1]);
                }
        }
        stage++; if (stage >= NSTAGE) stage = 0;
    }

    #pragma unroll
    for (int mt = 0; mt < 4; mt++) {
        int m0 = bm + wm * 64 + mt * 16 + (lane >> 2);
        #pragma unroll
        for (int nt = 0; nt < 4; nt++) {
            int n = bn + wn * 32 + nt * 8 + (lane & 3) * 2;
            float bx = bias[n], by = bias[n + 1];
            *(__half2*)(C + (size_t)m0 * QKV_N + n) =
                __floats2half2_rn(acc[mt][nt][0] + bx, acc[mt][nt][1] + by);
            *(__half2*)(C + (size_t)(m0 + 8) * QKV_N + n) =
                __floats2half2_rn(acc[mt][nt][2] + bx, acc[mt][nt][3] + by);
        }
    }
}

// ---------------------------------------------------------------------------
// GEMM2: BM=64, BN=128, BK=32, 8 warps (2x4), warp tile 32x32,
// 3-stage cp.async, 3 CTAs/SM. fp32 out, ldc=1536, coff=768.
// ---------------------------------------------------------------------------
#define STAGE2_BYTES 12288
#define GEMM2_SMEM   (NSTAGE * STAGE2_BYTES)

__device__ __forceinline__ void load_stage2(uint32_t smb, int stage,
                                            const __half* A, const __half* B,
                                            int bm, int bn, int k0, int tid)
{
    const uint32_t base = smb + stage * STAGE2_BYTES;
    {   // A: 64 rows x 4 chunks = 256 ops
        int row = tid >> 2, c = tid & 3;
        const char* ga = (const char*)(A + (size_t)(bm + row) * KDIM + k0 + c * 8);
        CP_ASYNC16(base + swz_off(row, c), ga);
    }
    #pragma unroll
    for (int i = 0; i < 2; i++) {   // B: 128 rows x 4 chunks = 512 ops
        int idx = tid + i * 256;
        int row = idx >> 2, c = idx & 3;
        const char* gb = (const char*)(B + (size_t)(bn + row) * KDIM + k0 + c * 8);
        CP_ASYNC16(base + 4096 + swz_off(row, c), gb);
    }
}

__global__ __launch_bounds__(256, 3)
void gemm2_fp16(const __half* __restrict__ A, const __half* __restrict__ B,
                const float* __restrict__ bias, float* __restrict__ C)
{
    extern __shared__ char sm[];
    const uint32_t smb = smem_u32(sm);
    const int tid  = threadIdx.x;
    const int lane = tid & 31;
    const int wid  = tid >> 5;
    const int wm   = wid & 1;       // 2 warps over M (32 rows)
    const int wn   = wid >> 1;      // 4 warps over N (32 cols)
    const int bm = blockIdx.y * 64;
    const int bn = blockIdx.x * 128;

    float acc[2][4][4];
    #pragma unroll
    for (int i = 0; i < 2; i++)
        #pragma unroll
        for (int j = 0; j < 4; j++)
            #pragma unroll
            for (int r = 0; r < 4; r++) acc[i][j][r] = 0.f;

    load_stage2(smb, 0, A, B, bm, bn, 0, tid);
    CP_COMMIT();
    load_stage2(smb, 1, A, B, bm, bn, BK, tid);
    CP_COMMIT();

    const int lane15 = lane & 15;
    const int aChunkSel = lane >> 4;
    const int bRow = ((lane & 16) >> 1) + (lane & 7);
    const int bChunkSel = (lane >> 3) & 1;

    int stage = 0;
    for (int c = 0; c < CHUNKS; c++) {
        if (c == CHUNKS - 1) { CP_WAIT0(); } else { CP_WAIT1(); }
        __syncthreads();
        if (c + 2 < CHUNKS) {
            int ns = stage + 2; if (ns >= NSTAGE) ns -= NSTAGE;
            load_stage2(smb, ns, A, B, bm, bn, (c + 2) * BK, tid);
            CP_COMMIT();
        }
        const uint32_t base = smb + stage * STAGE2_BYTES;

        #pragma unroll
        for (int ks = 0; ks < 2; ks++) {
            const int c0 = ks * 2;
            uint32_t af[2][4], bf[2][4];
            #pragma unroll
            for (int mt = 0; mt < 2; mt++) {
                int row = wm * 32 + mt * 16 + lane15;
                LDSM4(af[mt], base + swz_off(row, c0 + aChunkSel));
            }
            #pragma unroll
            for (int bt = 0; bt < 2; bt++) {
                int row = wn * 32 + bt * 16 + bRow;
                LDSM4(bf[bt], base + 4096 + swz_off(row, c0 + bChunkSel));
            }
            #pragma unroll
            for (int mt = 0; mt < 2; mt++)
                #pragma unroll
                for (int nt = 0; nt < 4; nt++) {
                    const uint32_t* bp = bf[nt >> 1] + ((nt & 1) << 1);
                    MMA16816(acc[mt][nt], af[mt], bp[0], bp[1]);
                }
        }
        stage++; if (stage >= NSTAGE) stage = 0;
    }

    #pragma unroll
    for (int mt = 0; mt < 2; mt++) {
        int m0 = bm + wm * 32 + mt * 16 + (lane >> 2);
        #pragma unroll
        for (int nt = 0; nt < 4; nt++) {
            int n = bn + wn * 32 + nt * 8 + (lane & 3) * 2;
            float bx = bias[n], by = bias[n + 1];
            *(float2*)(C + (size_t)m0 * (2*D_MODEL) + D_MODEL + n) =
                make_float2(acc[mt][nt][0] + bx, acc[mt][nt][1] + by);
            *(float2*)(C + (size_t)(m0 + 8) * (2*D_MODEL) + D_MODEL + n) =
                make_float2(acc[mt][nt][2] + bx, acc[mt][nt][3] + by);
        }
    }
}

// ---------------------------------------------------------------------------
// Attention v3: 2 warps per line (4 heads each), 8 lanes/head, 12 dims/lane.
// Fused copy of main -> out[:, :768].
// ---------------------------------------------------------------------------
__global__ __launch_bounds__(256)
void attn_kernel(const __half* __restrict__ P, __half* __restrict__ ctx,
                 const float* __restrict__ mn, float* __restrict__ out)
{
    const int warp = threadIdx.x >> 5;
    const int lane = threadIdx.x & 31;
    const int n    = blockIdx.x * 4 + (warp >> 1);
    const int half = warp & 1;
    const int dimoff = half * 384 + (lane >> 3) * HD + (lane & 7) * 12;

    const float scale = rsqrtf((float)HD);

    float qf[12];
    {
        const uint2* qp = (const uint2*)(P + (size_t)(n + OVERLAP) * QKV_N + dimoff);
        #pragma unroll
        for (int t = 0; t < 3; t++) {
            uint2 u = qp[t];
            const __half2* h2 = (const __half2*)&u;
            #pragma unroll
            for (int j = 0; j < 2; j++) {
                float2 f = __half22float2(h2[j]);
                qf[t*4 + 2*j]     = f.x * scale;
                qf[t*4 + 2*j + 1] = f.y * scale;
            }
        }
    }

    float s[W_KEYS];
    #pragma unroll
    for (int w = 0; w < W_KEYS; w++) {
        int off = (w < 8) ? (-OVERLAP + GAP * w) : (GAP * (w - 7));
        const uint2* kp = (const uint2*)(P + (size_t)(n + OVERLAP + off) * QKV_N + D_MODEL + dimoff);
        float p = 0.f;
        #pragma unroll
        for (int t = 0; t < 3; t++) {
            uint2 u = kp[t];
            const __half2* h2 = (const __half2*)&u;
            #pragma unroll
            for (int j = 0; j < 2; j++) {
                float2 f = __half22float2(h2[j]);
                p = fmaf(qf[t*4 + 2*j],     f.x, p);
                p = fmaf(qf[t*4 + 2*j + 1], f.y, p);
            }
        }
        p += __shfl_xor_sync(0xffffffffu, p, 1);
        p += __shfl_xor_sync(0xffffffffu, p, 2);
        p += __shfl_xor_sync(0xffffffffu, p, 4);
        s[w] = p;
    }

    float m = s[0];
    #pragma unroll
    for (int w = 1; w < W_KEYS; w++) m = fmaxf(m, s[w]);
    float sum = 0.f;
    #pragma unroll
    for (int w = 0; w < W_KEYS; w++) { s[w] = __expf(s[w] - m); sum += s[w]; }
    float inv = 1.f / sum;

    float c[12];
    #pragma unroll
    for (int j = 0; j < 12; j++) c[j] = 0.f;
    #pragma unroll
    for (int w = 0; w < W_KEYS; w++) {
        int off = (w < 8) ? (-OVERLAP + GAP * w) : (GAP * (w - 7));
        const uint2* vp = (const uint2*)(P + (size_t)(n + OVERLAP + off) * QKV_N + 2*D_MODEL + dimoff);
        float p = s[w] * inv;
        #pragma unroll
        for (int t = 0; t < 3; t++) {
            uint2 u = vp[t];
            const __half2* h2 = (const __half2*)&u;
            #pragma unroll
            for (int j = 0; j < 2; j++) {
                float2 f = __half22float2(h2[j]);
                c[t*4 + 2*j]     = fmaf(p, f.x, c[t*4 + 2*j]);
                c[t*4 + 2*j + 1] = fmaf(p, f.y, c[t*4 + 2*j + 1]);
            }
        }
    }

    uint2* cp = (uint2*)(ctx + (size_t)n * D_MODEL + dimoff);
    #pragma unroll
    for (int t = 0; t < 3; t++) {
        uint2 u;
        __half2* h2 = (__half2*)&u;
        h2[0] = __floats2half2_rn(c[t*4 + 0], c[t*4 + 1]);
        h2[1] = __floats2half2_rn(c[t*4 + 2], c[t*4 + 3]);
        cp[t] = u;
    }

    {
        int b0 = blockIdx.x * 768 + threadIdx.x;
        #pragma unroll
        for (int i = 0; i < 3; i++) {
            int idx = b0 + i * 256;
            int row = idx / 192, c4 = idx % 192;
            ((float4*)(out + (size_t)row * 2 * D_MODEL))[c4] =
                ((const float4*)(mn + (size_t)row * D_MODEL))[c4];
        }
    }
}

// ---------------------------------------------------------------------------
extern "C" void kernel_launch(void* const* d_in, const int* in_sizes, int n_in,
                              void* d_out, int out_size)
{
    const float* mn   = (const float*)d_in[0];
    const float* bg   = (const float*)d_in[1];
    const float* ed   = (const float*)d_in[2];
    const float* wqkv = (const float*)d_in[3];
    const float* bqkv = (const float*)d_in[4];
    const float* wo   = (const float*)d_in[5];
    const float* bo   = (const float*)d_in[6];
    float* out = (float*)d_out;

    void *pP, *pc, *pw1, *pw2, *pcx;
    cudaGetSymbolAddress(&pP,  g_P);
    cudaGetSymbolAddress(&pc,  g_comb);
    cudaGetSymbolAddress(&pw1, g_w1);
    cudaGetSymbolAddress(&pw2, g_w2);
    cudaGetSymbolAddress(&pcx, g_ctx);

    cudaFuncSetAttribute(gemm1_fp16, cudaFuncAttributeMaxDynamicSharedMemorySize, GEMM1_SMEM);
    cudaFuncSetAttribute(gemm2_fp16, cudaFuncAttributeMaxDynamicSharedMemorySize, GEMM2_SMEM);

    // prep (fused conversions, MLP=4)
    prep_kernel<<<(PREP_TOTAL + 1023) / 1024, 256>>>(mn, bg, ed, wqkv, wo);

    // GEMM1: P = comb @ wqkv^T + bqkv  (Mpad=8320, N=2304) -> fp16 P
    {
        dim3 grid(QKV_N / 128, M_PAD / 128);
        gemm1_fp16<<<grid, 256, GEMM1_SMEM>>>(
            (const __half*)pc, (const __half*)pw1, bqkv, (__half*)pP);
    }
    // attention (+ fused main copy) -> ctx fp16
    attn_kernel<<<N_LINES / 4, 256>>>((const __half*)pP, (__half*)pcx, mn, out);

    // GEMM2: out[:,768:] = ctx @ wo^T + bo  (M=8192, N=768) -> fp32
    {
        dim3 grid(D_MODEL / 128, N_LINES / 64);
        gemm2_fp16<<<grid, 256, GEMM2_SMEM>>>(
            (const __half*)pcx, (const __half*)pw2, bo, out);
    }
}

// round 9
// speedup vs baseline: 6.4337x; 1.0524x over previous
#include <cuda_runtime.h>
#include <cuda_fp16.h>
#include <cstdint>

#define N_LINES   8192
#define D_MODEL   768
#define HD        96
#define OVERLAP   32
#define GAP       4
#define W_KEYS    16
#define M_COMB    (N_LINES + 2*OVERLAP)   // 8256
#define M_PAD     8320                    // 65*128
#define QKV_N     (3*D_MODEL)             // 2304
#define KDIM      768
#define BK        64
#define CHUNKS    (KDIM / BK)             // 12

// ---- scratch (device globals, padded M) ----
__device__ __half g_comb[(size_t)M_PAD * KDIM];
__device__ __half g_P[(size_t)M_PAD * QKV_N];
__device__ __half g_w1[(size_t)QKV_N * KDIM];
__device__ __half g_w2[(size_t)D_MODEL * KDIM];
__device__ __half g_ctx[(size_t)N_LINES * KDIM];

// ---------------- PTX helpers ----------------
__device__ __forceinline__ uint32_t smem_u32(const void* p) {
    uint32_t a;
    asm("{ .reg .u64 t; cvta.to.shared.u64 t, %1; cvt.u32.u64 %0, t; }" : "=r"(a) : "l"(p));
    return a;
}

#define CP_ASYNC16(s, g) \
    asm volatile("cp.async.cg.shared.global [%0], [%1], 16;" :: "r"(s), "l"(g))
#define CP_COMMIT()  asm volatile("cp.async.commit_group;")
#define CP_WAIT0()   asm volatile("cp.async.wait_group 0;")
#define CP_WAIT1()   asm volatile("cp.async.wait_group 1;")

#define LDSM4(r, addr) \
    asm volatile("ldmatrix.sync.aligned.m8n8.x4.shared.b16 {%0,%1,%2,%3}, [%4];" \
        : "=r"((r)[0]), "=r"((r)[1]), "=r"((r)[2]), "=r"((r)[3]) : "r"(addr))

#define MMA16816(d, a, b0, b1) \
    asm volatile("mma.sync.aligned.m16n8k16.row.col.f32.f16.f16.f32 " \
        "{%0,%1,%2,%3}, {%4,%5,%6,%7}, {%8,%9}, {%0,%1,%2,%3};" \
        : "+f"((d)[0]), "+f"((d)[1]), "+f"((d)[2]), "+f"((d)[3]) \
        : "r"((a)[0]), "r"((a)[1]), "r"((a)[2]), "r"((a)[3]), "r"(b0), "r"(b1))

// 128B-row layout with 8-way XOR swizzle; rows of 64 halves (128B), chunk=16B unit 0..7
__device__ __forceinline__ uint32_t swz64(int row, int chunk) {
    return (uint32_t)(row * 128 + ((chunk ^ (row & 7)) << 4));
}

// ---------------------------------------------------------------------------
// fused prep: comb build + w1 + w2 fp32->fp16, 4 float4 per thread (MLP=4)
// ---------------------------------------------------------------------------
#define COMB4 (M_COMB * KDIM / 4)
#define W14   (QKV_N * KDIM / 4)
#define W24   (D_MODEL * KDIM / 4)
#define PREP_TOTAL (COMB4 + W14 + W24)

__global__ void prep_kernel(const float* __restrict__ mn,
                            const float* __restrict__ bg,
                            const float* __restrict__ ed,
                            const float* __restrict__ w1,
                            const float* __restrict__ w2)
{
    int base = blockIdx.x * 1024 + threadIdx.x;
    float4 v[4];
    __half* dsts[4];
    #pragma unroll
    for (int t = 0; t < 4; t++) {
        int i = base + t * 256;
        const float4* src = nullptr;
        __half* dst = nullptr;
        if (i < COMB4) {
            int row = i / (KDIM/4), c4 = i % (KDIM/4);
            if (row < OVERLAP)                src = (const float4*)(bg + (size_t)row * KDIM) + c4;
            else if (row < OVERLAP + N_LINES) src = (const float4*)(mn + (size_t)(row - OVERLAP) * KDIM) + c4;
            else                              src = (const float4*)(ed + (size_t)(row - OVERLAP - N_LINES) * KDIM) + c4;
            dst = g_comb + (size_t)i * 4;
        } else if (i < COMB4 + W14) {
            int j = i - COMB4;
            src = (const float4*)w1 + j;
            dst = g_w1 + (size_t)j * 4;
        } else if (i < PREP_TOTAL) {
            int j = i - COMB4 - W14;
            src = (const float4*)w2 + j;
            dst = g_w2 + (size_t)j * 4;
        }
        dsts[t] = dst;
        if (dst) v[t] = *src;
    }
    #pragma unroll
    for (int t = 0; t < 4; t++) {
        if (dsts[t]) {
            __half2* d2 = (__half2*)dsts[t];
            d2[0] = __floats2half2_rn(v[t].x, v[t].y);
            d2[1] = __floats2half2_rn(v[t].z, v[t].w);
        }
    }
}

// ---------------------------------------------------------------------------
// GEMM1: BM=128, BN=128, BK=64, 8 warps (2x4), warp tile 64x32,
// 3-stage cp.async, 2 CTAs/SM. A 16KB + B 16KB = 32KB/stage. fp16 out.
// ---------------------------------------------------------------------------
#define STAGE1_BYTES 32768
#define NSTAGE       3
#define GEMM1_SMEM   (NSTAGE * STAGE1_BYTES)

__device__ __forceinline__ void load_stage1(uint32_t smb, int stage,
                                            const __half* A, const __half* B,
                                            int bm, int bn, int k0, int tid)
{
    const uint32_t base = smb + stage * STAGE1_BYTES;
    #pragma unroll
    for (int i = 0; i < 4; i++) {
        int idx = tid + i * 256;               // 0..1023
        int row = idx >> 3, c = idx & 7;
        const char* ga = (const char*)(A + (size_t)(bm + row) * KDIM + k0 + c * 8);
        CP_ASYNC16(base + swz64(row, c), ga);
        const char* gb = (const char*)(B + (size_t)(bn + row) * KDIM + k0 + c * 8);
        CP_ASYNC16(base + 16384 + swz64(row, c), gb);
    }
}

__global__ __launch_bounds__(256, 2)
void gemm1_fp16(const __half* __restrict__ A, const __half* __restrict__ B,
                const float* __restrict__ bias, __half* __restrict__ C)
{
    extern __shared__ char sm[];
    const uint32_t smb = smem_u32(sm);
    const int tid  = threadIdx.x;
    const int lane = tid & 31;
    const int wid  = tid >> 5;
    const int wm   = wid & 1;
    const int wn   = wid >> 1;
    const int bm = blockIdx.y * 128;
    const int bn = blockIdx.x * 128;

    float acc[4][4][4];
    #pragma unroll
    for (int i = 0; i < 4; i++)
        #pragma unroll
        for (int j = 0; j < 4; j++)
            #pragma unroll
            for (int r = 0; r < 4; r++) acc[i][j][r] = 0.f;

    load_stage1(smb, 0, A, B, bm, bn, 0, tid);
    CP_COMMIT();
    load_stage1(smb, 1, A, B, bm, bn, BK, tid);
    CP_COMMIT();

    const int lane15 = lane & 15;
    const int aChunkSel = lane >> 4;               // 0/1
    const int bRow = ((lane & 16) >> 1) + (lane & 7);
    const int bChunkSel = (lane >> 3) & 1;         // 0/1

    int stage = 0;
    for (int c = 0; c < CHUNKS; c++) {
        if (c == CHUNKS - 1) { CP_WAIT0(); } else { CP_WAIT1(); }
        __syncthreads();
        if (c + 2 < CHUNKS) {
            int ns = stage + 2; if (ns >= NSTAGE) ns -= NSTAGE;
            load_stage1(smb, ns, A, B, bm, bn, (c + 2) * BK, tid);
            CP_COMMIT();
        }
        const uint32_t base = smb + stage * STAGE1_BYTES;

        #pragma unroll
        for (int ks = 0; ks < 4; ks++) {           // 4 x K16 per BK=64
            const int c0 = ks * 2;
            uint32_t af[4][4], bf[2][4];
            #pragma unroll
            for (int mt = 0; mt < 4; mt++) {
                int row = wm * 64 + mt * 16 + lane15;
                LDSM4(af[mt], base + swz64(row, c0 + aChunkSel));
            }
            #pragma unroll
            for (int bt = 0; bt < 2; bt++) {
                int row = wn * 32 + bt * 16 + bRow;
                LDSM4(bf[bt], base + 16384 + swz64(row, c0 + bChunkSel));
            }
            #pragma unroll
            for (int mt = 0; mt < 4; mt++)
                #pragma unroll
                for (int nt = 0; nt < 4; nt++) {
                    const uint32_t* bp = bf[nt >> 1] + ((nt & 1) << 1);
                    MMA16816(acc[mt][nt], af[mt], bp[0], bp[1]);
                }
        }
        stage++; if (stage >= NSTAGE) stage = 0;
    }

    #pragma unroll
    for (int mt = 0; mt < 4; mt++) {
        int m0 = bm + wm * 64 + mt * 16 + (lane >> 2);
        #pragma unroll
        for (int nt = 0; nt < 4; nt++) {
            int n = bn + wn * 32 + nt * 8 + (lane & 3) * 2;
            float bx = bias[n], by = bias[n + 1];
            *(__half2*)(C + (size_t)m0 * QKV_N + n) =
                __floats2half2_rn(acc[mt][nt][0] + bx, acc[mt][nt][1] + by);
            *(__half2*)(C + (size_t)(m0 + 8) * QKV_N + n) =
                __floats2half2_rn(acc[mt][nt][2] + bx, acc[mt][nt][3] + by);
        }
    }
}

// ---------------------------------------------------------------------------
// GEMM2: BM=64, BN=128, BK=64, 8 warps (2x4), warp tile 32x32,
// 3-stage cp.async, 3 CTAs/SM. A 8KB + B 16KB = 24KB/stage. fp32 out.
// ---------------------------------------------------------------------------
#define STAGE2_BYTES 24576
#define GEMM2_SMEM   (NSTAGE * STAGE2_BYTES)

__device__ __forceinline__ void load_stage2(uint32_t smb, int stage,
                                            const __half* A, const __half* B,
                                            int bm, int bn, int k0, int tid)
{
    const uint32_t base = smb + stage * STAGE2_BYTES;
    #pragma unroll
    for (int i = 0; i < 2; i++) {                  // A: 64 rows x 8 chunks = 512
        int idx = tid + i * 256;
        int row = idx >> 3, c = idx & 7;
        const char* ga = (const char*)(A + (size_t)(bm + row) * KDIM + k0 + c * 8);
        CP_ASYNC16(base + swz64(row, c), ga);
    }
    #pragma unroll
    for (int i = 0; i < 4; i++) {                  // B: 128 rows x 8 chunks = 1024
        int idx = tid + i * 256;
        int row = idx >> 3, c = idx & 7;
        const char* gb = (const char*)(B + (size_t)(bn + row) * KDIM + k0 + c * 8);
        CP_ASYNC16(base + 8192 + swz64(row, c), gb);
    }
}

__global__ __launch_bounds__(256, 3)
void gemm2_fp16(const __half* __restrict__ A, const __half* __restrict__ B,
                const float* __restrict__ bias, float* __restrict__ C)
{
    extern __shared__ char sm[];
    const uint32_t smb = smem_u32(sm);
    const int tid  = threadIdx.x;
    const int lane = tid & 31;
    const int wid  = tid >> 5;
    const int wm   = wid & 1;
    const int wn   = wid >> 1;
    const int bm = blockIdx.y * 64;
    const int bn = blockIdx.x * 128;

    float acc[2][4][4];
    #pragma unroll
    for (int i = 0; i < 2; i++)
        #pragma unroll
        for (int j = 0; j < 4; j++)
            #pragma unroll
            for (int r = 0; r < 4; r++) acc[i][j][r] = 0.f;

    load_stage2(smb, 0, A, B, bm, bn, 0, tid);
    CP_COMMIT();
    load_stage2(smb, 1, A, B, bm, bn, BK, tid);
    CP_COMMIT();

    const int lane15 = lane & 15;
    const int aChunkSel = lane >> 4;
    const int bRow = ((lane & 16) >> 1) + (lane & 7);
    const int bChunkSel = (lane >> 3) & 1;

    int stage = 0;
    for (int c = 0; c < CHUNKS; c++) {
        if (c == CHUNKS - 1) { CP_WAIT0(); } else { CP_WAIT1(); }
        __syncthreads();
        if (c + 2 < CHUNKS) {
            int ns = stage + 2; if (ns >= NSTAGE) ns -= NSTAGE;
            load_stage2(smb, ns, A, B, bm, bn, (c + 2) * BK, tid);
            CP_COMMIT();
        }
        const uint32_t base = smb + stage * STAGE2_BYTES;

        #pragma unroll
        for (int ks = 0; ks < 4; ks++) {
            const int c0 = ks * 2;
            uint32_t af[2][4], bf[2][4];
            #pragma unroll
            for (int mt = 0; mt < 2; mt++) {
                int row = wm * 32 + mt * 16 + lane15;
                LDSM4(af[mt], base + swz64(row, c0 + aChunkSel));
            }
            #pragma unroll
            for (int bt = 0; bt < 2; bt++) {
                int row = wn * 32 + bt * 16 + bRow;
                LDSM4(bf[bt], base + 8192 + swz64(row, c0 + bChunkSel));
            }
            #pragma unroll
            for (int mt = 0; mt < 2; mt++)
                #pragma unroll
                for (int nt = 0; nt < 4; nt++) {
                    const uint32_t* bp = bf[nt >> 1] + ((nt & 1) << 1);
                    MMA16816(acc[mt][nt], af[mt], bp[0], bp[1]);
                }
        }
        stage++; if (stage >= NSTAGE) stage = 0;
    }

    #pragma unroll
    for (int mt = 0; mt < 2; mt++) {
        int m0 = bm + wm * 32 + mt * 16 + (lane >> 2);
        #pragma unroll
        for (int nt = 0; nt < 4; nt++) {
            int n = bn + wn * 32 + nt * 8 + (lane & 3) * 2;
            float bx = bias[n], by = bias[n + 1];
            *(float2*)(C + (size_t)m0 * (2*D_MODEL) + D_MODEL + n) =
                make_float2(acc[mt][nt][0] + bx, acc[mt][nt][1] + by);
            *(float2*)(C + (size_t)(m0 + 8) * (2*D_MODEL) + D_MODEL + n) =
                make_float2(acc[mt][nt][2] + bx, acc[mt][nt][3] + by);
        }
    }
}

// ---------------------------------------------------------------------------
// Attention: 2 warps per line (4 heads each), 8 lanes/head, 12 dims/lane.
// Fused copy of main -> out[:, :768].
// ---------------------------------------------------------------------------
__global__ __launch_bounds__(256)
void attn_kernel(const __half* __restrict__ P, __half* __restrict__ ctx,
                 const float* __restrict__ mn, float* __restrict__ out)
{
    const int warp = threadIdx.x >> 5;
    const int lane = threadIdx.x & 31;
    const int n    = blockIdx.x * 4 + (warp >> 1);
    const int half = warp & 1;
    const int dimoff = half * 384 + (lane >> 3) * HD + (lane & 7) * 12;

    const float scale = rsqrtf((float)HD);

    float qf[12];
    {
        const uint2* qp = (const uint2*)(P + (size_t)(n + OVERLAP) * QKV_N + dimoff);
        #pragma unroll
        for (int t = 0; t < 3; t++) {
            uint2 u = qp[t];
            const __half2* h2 = (const __half2*)&u;
            #pragma unroll
            for (int j = 0; j < 2; j++) {
                float2 f = __half22float2(h2[j]);
                qf[t*4 + 2*j]     = f.x * scale;
                qf[t*4 + 2*j + 1] = f.y * scale;
            }
        }
    }

    float s[W_KEYS];
    #pragma unroll
    for (int w = 0; w < W_KEYS; w++) {
        int off = (w < 8) ? (-OVERLAP + GAP * w) : (GAP * (w - 7));
        const uint2* kp = (const uint2*)(P + (size_t)(n + OVERLAP + off) * QKV_N + D_MODEL + dimoff);
        float p = 0.f;
        #pragma unroll
        for (int t = 0; t < 3; t++) {
            uint2 u = kp[t];
            const __half2* h2 = (const __half2*)&u;
            #pragma unroll
            for (int j = 0; j < 2; j++) {
                float2 f = __half22float2(h2[j]);
                p = fmaf(qf[t*4 + 2*j],     f.x, p);
                p = fmaf(qf[t*4 + 2*j + 1], f.y, p);
            }
        }
        p += __shfl_xor_sync(0xffffffffu, p, 1);
        p += __shfl_xor_sync(0xffffffffu, p, 2);
        p += __shfl_xor_sync(0xffffffffu, p, 4);
        s[w] = p;
    }

    float m = s[0];
    #pragma unroll
    for (int w = 1; w < W_KEYS; w++) m = fmaxf(m, s[w]);
    float sum = 0.f;
    #pragma unroll
    for (int w = 0; w < W_KEYS; w++) { s[w] = __expf(s[w] - m); sum += s[w]; }
    float inv = 1.f / sum;

    float c[12];
    #pragma unroll
    for (int j = 0; j < 12; j++) c[j] = 0.f;
    #pragma unroll
    for (int w = 0; w < W_KEYS; w++) {
        int off = (w < 8) ? (-OVERLAP + GAP * w) : (GAP * (w - 7));
        const uint2* vp = (const uint2*)(P + (size_t)(n + OVERLAP + off) * QKV_N + 2*D_MODEL + dimoff);
        float p = s[w] * inv;
        #pragma unroll
        for (int t = 0; t < 3; t++) {
            uint2 u = vp[t];
            const __half2* h2 = (const __half2*)&u;
            #pragma unroll
            for (int j = 0; j < 2; j++) {
                float2 f = __half22float2(h2[j]);
                c[t*4 + 2*j]     = fmaf(p, f.x, c[t*4 + 2*j]);
                c[t*4 + 2*j + 1] = fmaf(p, f.y, c[t*4 + 2*j + 1]);
            }
        }
    }

    uint2* cp = (uint2*)(ctx + (size_t)n * D_MODEL + dimoff);
    #pragma unroll
    for (int t = 0; t < 3; t++) {
        uint2 u;
        __half2* h2 = (__half2*)&u;
        h2[0] = __floats2half2_rn(c[t*4 + 0], c[t*4 + 1]);
        h2[1] = __floats2half2_rn(c[t*4 + 2], c[t*4 + 3]);
        cp[t] = u;
    }

    {
        int b0 = blockIdx.x * 768 + threadIdx.x;
        #pragma unroll
        for (int i = 0; i < 3; i++) {
            int idx = b0 + i * 256;
            int row = idx / 192, c4 = idx % 192;
            ((float4*)(out + (size_t)row * 2 * D_MODEL))[c4] =
                ((const float4*)(mn + (size_t)row * D_MODEL))[c4];
        }
    }
}

// ---------------------------------------------------------------------------
extern "C" void kernel_launch(void* const* d_in, const int* in_sizes, int n_in,
                              void* d_out, int out_size)
{
    const float* mn   = (const float*)d_in[0];
    const float* bg   = (const float*)d_in[1];
    const float* ed   = (const float*)d_in[2];
    const float* wqkv = (const float*)d_in[3];
    const float* bqkv = (const float*)d_in[4];
    const float* wo   = (const float*)d_in[5];
    const float* bo   = (const float*)d_in[6];
    float* out = (float*)d_out;

    void *pP, *pc, *pw1, *pw2, *pcx;
    cudaGetSymbolAddress(&pP,  g_P);
    cudaGetSymbolAddress(&pc,  g_comb);
    cudaGetSymbolAddress(&pw1, g_w1);
    cudaGetSymbolAddress(&pw2, g_w2);
    cudaGetSymbolAddress(&pcx, g_ctx);

    cudaFuncSetAttribute(gemm1_fp16, cudaFuncAttributeMaxDynamicSharedMemorySize, GEMM1_SMEM);
    cudaFuncSetAttribute(gemm2_fp16, cudaFuncAttributeMaxDynamicSharedMemorySize, GEMM2_SMEM);

    // prep (fused conversions, MLP=4)
    prep_kernel<<<(PREP_TOTAL + 1023) / 1024, 256>>>(mn, bg, ed, wqkv, wo);

    // GEMM1: P = comb @ wqkv^T + bqkv  (Mpad=8320, N=2304) -> fp16 P
    {
        dim3 grid(QKV_N / 128, M_PAD / 128);
        gemm1_fp16<<<grid, 256, GEMM1_SMEM>>>(
            (const __half*)pc, (const __half*)pw1, bqkv, (__half*)pP);
    }
    // attention (+ fused main copy) -> ctx fp16
    attn_kernel<<<N_LINES / 4, 256>>>((const __half*)pP, (__half*)pcx, mn, out);

    // GEMM2: out[:,768:] = ctx @ wo^T + bo  (M=8192, N=768) -> fp32
    {
        dim3 grid(D_MODEL / 128, N_LINES / 64);
        gemm2_fp16<<<grid, 256, GEMM2_SMEM>>>(
            (const __half*)pcx, (const __half*)pw2, bo, out);
    }
}

// round 10
// speedup vs baseline: 6.4733x; 1.0062x over previous
#include <cuda_runtime.h>
#include <cuda_fp16.h>
#include <cstdint>

#define N_LINES   8192
#define D_MODEL   768
#define HD        96
#define OVERLAP   32
#define GAP       4
#define W_KEYS    16
#define M_COMB    (N_LINES + 2*OVERLAP)   // 8256
#define M_PAD     8320                    // 65*128
#define QKV_N     (3*D_MODEL)             // 2304
#define KDIM      768

// ---- scratch (device globals, padded M) ----
__device__ __half g_comb[(size_t)M_PAD * KDIM];
__device__ __half g_P[(size_t)M_PAD * QKV_N];
__device__ __half g_w1[(size_t)QKV_N * KDIM];
__device__ __half g_w2[(size_t)D_MODEL * KDIM];
__device__ __half g_ctx[(size_t)N_LINES * KDIM];

// ---------------- PTX helpers ----------------
__device__ __forceinline__ uint32_t smem_u32(const void* p) {
    uint32_t a;
    asm("{ .reg .u64 t; cvta.to.shared.u64 t, %1; cvt.u32.u64 %0, t; }" : "=r"(a) : "l"(p));
    return a;
}

#define CP_ASYNC16(s, g) \
    asm volatile("cp.async.cg.shared.global [%0], [%1], 16;" :: "r"(s), "l"(g))
#define CP_COMMIT()  asm volatile("cp.async.commit_group;")
#define CP_WAIT0()   asm volatile("cp.async.wait_group 0;")
#define CP_WAIT1()   asm volatile("cp.async.wait_group 1;")

#define LDSM4(r, addr) \
    asm volatile("ldmatrix.sync.aligned.m8n8.x4.shared.b16 {%0,%1,%2,%3}, [%4];" \
        : "=r"((r)[0]), "=r"((r)[1]), "=r"((r)[2]), "=r"((r)[3]) : "r"(addr))

#define MMA16816(d, a, b0, b1) \
    asm volatile("mma.sync.aligned.m16n8k16.row.col.f32.f16.f16.f32 " \
        "{%0,%1,%2,%3}, {%4,%5,%6,%7}, {%8,%9}, {%0,%1,%2,%3};" \
        : "+f"((d)[0]), "+f"((d)[1]), "+f"((d)[2]), "+f"((d)[3]) \
        : "r"((a)[0]), "r"((a)[1]), "r"((a)[2]), "r"((a)[3]), "r"(b0), "r"(b1))

// 128B-row layout with 8-way XOR swizzle; rows of 64 halves, chunk = 16B unit 0..7
__device__ __forceinline__ uint32_t swz64(int row, int chunk) {
    return (uint32_t)(row * 128 + ((chunk ^ (row & 7)) << 4));
}

// ---------------------------------------------------------------------------
// fused prep: comb build + w1 + w2 fp32->fp16, 4 float4 per thread (MLP=4)
// ---------------------------------------------------------------------------
#define COMB4 (M_COMB * KDIM / 4)
#define W14   (QKV_N * KDIM / 4)
#define W24   (D_MODEL * KDIM / 4)
#define PREP_TOTAL (COMB4 + W14 + W24)

__global__ void prep_kernel(const float* __restrict__ mn,
                            const float* __restrict__ bg,
                            const float* __restrict__ ed,
                            const float* __restrict__ w1,
                            const float* __restrict__ w2)
{
    int base = blockIdx.x * 1024 + threadIdx.x;
    float4 v[4];
    __half* dsts[4];
    #pragma unroll
    for (int t = 0; t < 4; t++) {
        int i = base + t * 256;
        const float4* src = nullptr;
        __half* dst = nullptr;
        if (i < COMB4) {
            int row = i / (KDIM/4), c4 = i % (KDIM/4);
            if (row < OVERLAP)                src = (const float4*)(bg + (size_t)row * KDIM) + c4;
            else if (row < OVERLAP + N_LINES) src = (const float4*)(mn + (size_t)(row - OVERLAP) * KDIM) + c4;
            else                              src = (const float4*)(ed + (size_t)(row - OVERLAP - N_LINES) * KDIM) + c4;
            dst = g_comb + (size_t)i * 4;
        } else if (i < COMB4 + W14) {
            int j = i - COMB4;
            src = (const float4*)w1 + j;
            dst = g_w1 + (size_t)j * 4;
        } else if (i < PREP_TOTAL) {
            int j = i - COMB4 - W14;
            src = (const float4*)w2 + j;
            dst = g_w2 + (size_t)j * 4;
        }
        dsts[t] = dst;
        if (dst) v[t] = *src;
    }
    #pragma unroll
    for (int t = 0; t < 4; t++) {
        if (dsts[t]) {
            __half2* d2 = (__half2*)dsts[t];
            d2[0] = __floats2half2_rn(v[t].x, v[t].y);
            d2[1] = __floats2half2_rn(v[t].z, v[t].w);
        }
    }
}

// ---------------------------------------------------------------------------
// GEMM1: BM=128, BN=128, BK=64, 8 warps (2x4), warp tile 64x32,
// 3-stage cp.async, 2 CTAs/SM. fp16 out. (unchanged from R9)
// ---------------------------------------------------------------------------
#define BK1          64
#define CHUNKS1      (KDIM / BK1)          // 12
#define STAGE1_BYTES 32768
#define NSTAGE1      3
#define GEMM1_SMEM   (NSTAGE1 * STAGE1_BYTES)

__device__ __forceinline__ void load_stage1(uint32_t smb, int stage,
                                            const __half* A, const __half* B,
                                            int bm, int bn, int k0, int tid)
{
    const uint32_t base = smb + stage * STAGE1_BYTES;
    #pragma unroll
    for (int i = 0; i < 4; i++) {
        int idx = tid + i * 256;               // 0..1023
        int row = idx >> 3, c = idx & 7;
        const char* ga = (const char*)(A + (size_t)(bm + row) * KDIM + k0 + c * 8);
        CP_ASYNC16(base + swz64(row, c), ga);
        const char* gb = (const char*)(B + (size_t)(bn + row) * KDIM + k0 + c * 8);
        CP_ASYNC16(base + 16384 + swz64(row, c), gb);
    }
}

__global__ __launch_bounds__(256, 2)
void gemm1_fp16(const __half* __restrict__ A, const __half* __restrict__ B,
                const float* __restrict__ bias, __half* __restrict__ C)
{
    extern __shared__ char sm[];
    const uint32_t smb = smem_u32(sm);
    const int tid  = threadIdx.x;
    const int lane = tid & 31;
    const int wid  = tid >> 5;
    const int wm   = wid & 1;
    const int wn   = wid >> 1;
    const int bm = blockIdx.y * 128;
    const int bn = blockIdx.x * 128;

    float acc[4][4][4];
    #pragma unroll
    for (int i = 0; i < 4; i++)
        #pragma unroll
        for (int j = 0; j < 4; j++)
            #pragma unroll
            for (int r = 0; r < 4; r++) acc[i][j][r] = 0.f;

    load_stage1(smb, 0, A, B, bm, bn, 0, tid);
    CP_COMMIT();
    load_stage1(smb, 1, A, B, bm, bn, BK1, tid);
    CP_COMMIT();

    const int lane15 = lane & 15;
    const int aChunkSel = lane >> 4;
    const int bRow = ((lane & 16) >> 1) + (lane & 7);
    const int bChunkSel = (lane >> 3) & 1;

    int stage = 0;
    for (int c = 0; c < CHUNKS1; c++) {
        if (c == CHUNKS1 - 1) { CP_WAIT0(); } else { CP_WAIT1(); }
        __syncthreads();
        if (c + 2 < CHUNKS1) {
            int ns = stage + 2; if (ns >= NSTAGE1) ns -= NSTAGE1;
            load_stage1(smb, ns, A, B, bm, bn, (c + 2) * BK1, tid);
            CP_COMMIT();
        }
        const uint32_t base = smb + stage * STAGE1_BYTES;

        #pragma unroll
        for (int ks = 0; ks < 4; ks++) {
            const int c0 = ks * 2;
            uint32_t af[4][4], bf[2][4];
            #pragma unroll
            for (int mt = 0; mt < 4; mt++) {
                int row = wm * 64 + mt * 16 + lane15;
                LDSM4(af[mt], base + swz64(row, c0 + aChunkSel));
            }
            #pragma unroll
            for (int bt = 0; bt < 2; bt++) {
                int row = wn * 32 + bt * 16 + bRow;
                LDSM4(bf[bt], base + 16384 + swz64(row, c0 + bChunkSel));
            }
            #pragma unroll
            for (int mt = 0; mt < 4; mt++)
                #pragma unroll
                for (int nt = 0; nt < 4; nt++) {
                    const uint32_t* bp = bf[nt >> 1] + ((nt & 1) << 1);
                    MMA16816(acc[mt][nt], af[mt], bp[0], bp[1]);
                }
        }
        stage++; if (stage >= NSTAGE1) stage = 0;
    }

    #pragma unroll
    for (int mt = 0; mt < 4; mt++) {
        int m0 = bm + wm * 64 + mt * 16 + (lane >> 2);
        #pragma unroll
        for (int nt = 0; nt < 4; nt++) {
            int n = bn + wn * 32 + nt * 8 + (lane & 3) * 2;
            float bx = bias[n], by = bias[n + 1];
            *(__half2*)(C + (size_t)m0 * QKV_N + n) =
                __floats2half2_rn(acc[mt][nt][0] + bx, acc[mt][nt][1] + by);
            *(__half2*)(C + (size_t)(m0 + 8) * QKV_N + n) =
                __floats2half2_rn(acc[mt][nt][2] + bx, acc[mt][nt][3] + by);
        }
    }
}

// ---------------------------------------------------------------------------
// GEMM2 v2: BM=64, BN=128, BK=128 (two 64-col sub-tiles), 8 warps (2x4),
// warp tile 32x32, 2-stage smem pipeline, register double-buffered frags,
// 2 CTAs/SM. fp32 out, ldc=1536, coff=768.
// Stage layout: A0 @0 (8KB), A1 @8K, B0 @16K (16KB), B1 @32K. 48KB/stage.
// ---------------------------------------------------------------------------
#define BK2          128
#define CHUNKS2      (KDIM / BK2)          // 6
#define STAGE2_BYTES 49152
#define GEMM2_SMEM   (2 * STAGE2_BYTES)

__device__ __forceinline__ void load_stage2(uint32_t smb, int stage,
                                            const __half* A, const __half* B,
                                            int bm, int bn, int k0, int tid)
{
    const uint32_t base = smb + stage * STAGE2_BYTES;
    // A: 2 sub-tiles x 64 rows x 8 chunks = 1024 ops
    #pragma unroll
    for (int i = 0; i < 2; i++) {
        int idx = tid + i * 256;
        int row = idx >> 3, c = idx & 7;
        const char* ga0 = (const char*)(A + (size_t)(bm + row) * KDIM + k0 + c * 8);
        CP_ASYNC16(base + swz64(row, c), ga0);
        const char* ga1 = (const char*)(A + (size_t)(bm + row) * KDIM + k0 + 64 + c * 8);
        CP_ASYNC16(base + 8192 + swz64(row, c), ga1);
    }
    // B: 2 sub-tiles x 128 rows x 8 chunks = 2048 ops
    #pragma unroll
    for (int i = 0; i < 4; i++) {
        int idx = tid + i * 256;
        int row = idx >> 3, c = idx & 7;
        const char* gb0 = (const char*)(B + (size_t)(bn + row) * KDIM + k0 + c * 8);
        CP_ASYNC16(base + 16384 + swz64(row, c), gb0);
        const char* gb1 = (const char*)(B + (size_t)(bn + row) * KDIM + k0 + 64 + c * 8);
        CP_ASYNC16(base + 32768 + swz64(row, c), gb1);
    }
}

__global__ __launch_bounds__(256, 2)
void gemm2_fp16(const __half* __restrict__ A, const __half* __restrict__ B,
                const float* __restrict__ bias, float* __restrict__ C)
{
    extern __shared__ char sm[];
    const uint32_t smb = smem_u32(sm);
    const int tid  = threadIdx.x;
    const int lane = tid & 31;
    const int wid  = tid >> 5;
    const int wm   = wid & 1;
    const int wn   = wid >> 1;
    const int bm = blockIdx.y * 64;
    const int bn = blockIdx.x * 128;

    float acc[2][4][4];
    #pragma unroll
    for (int i = 0; i < 2; i++)
        #pragma unroll
        for (int j = 0; j < 4; j++)
            #pragma unroll
            for (int r = 0; r < 4; r++) acc[i][j][r] = 0.f;

    const int lane15 = lane & 15;
    const int aChunkSel = lane >> 4;
    const int bRow = ((lane & 16) >> 1) + (lane & 7);
    const int bChunkSel = (lane >> 3) & 1;

    load_stage2(smb, 0, A, B, bm, bn, 0, tid);
    CP_COMMIT();

    uint32_t af[2][2][4], bf[2][2][4];

    for (int c = 0; c < CHUNKS2; c++) {
        CP_WAIT0();
        __syncthreads();
        if (c + 1 < CHUNKS2) {
            load_stage2(smb, (c + 1) & 1, A, B, bm, bn, (c + 1) * BK2, tid);
            CP_COMMIT();
        }
        const uint32_t base = smb + (c & 1) * STAGE2_BYTES;

        // load ks=0 fragments
        {
            const int c0 = 0;
            #pragma unroll
            for (int mt = 0; mt < 2; mt++)
                LDSM4(af[0][mt], base + swz64(wm * 32 + mt * 16 + lane15, c0 + aChunkSel));
            #pragma unroll
            for (int bt = 0; bt < 2; bt++)
                LDSM4(bf[0][bt], base + 16384 + swz64(wn * 32 + bt * 16 + bRow, c0 + bChunkSel));
        }

        #pragma unroll
        for (int ks = 0; ks < 8; ks++) {
            const int cur = ks & 1, nxt = cur ^ 1;
            if (ks < 7) {
                const int kn = ks + 1;
                const int c0 = (kn & 3) * 2;
                const uint32_t aoff = base + ((kn >> 2) << 13);            // +8192 for sub-tile 1
                const uint32_t boff = base + 16384 + ((kn >> 2) << 14);    // +16384 for sub-tile 1
                #pragma unroll
                for (int mt = 0; mt < 2; mt++)
                    LDSM4(af[nxt][mt], aoff + swz64(wm * 32 + mt * 16 + lane15, c0 + aChunkSel));
                #pragma unroll
                for (int bt = 0; bt < 2; bt++)
                    LDSM4(bf[nxt][bt], boff + swz64(wn * 32 + bt * 16 + bRow, c0 + bChunkSel));
            }
            #pragma unroll
            for (int mt = 0; mt < 2; mt++)
                #pragma unroll
                for (int nt = 0; nt < 4; nt++) {
                    const uint32_t* bp = bf[cur][nt >> 1] + ((nt & 1) << 1);
                    MMA16816(acc[mt][nt], af[cur][mt], bp[0], bp[1]);
                }
        }
    }

    #pragma unroll
    for (int mt = 0; mt < 2; mt++) {
        int m0 = bm + wm * 32 + mt * 16 + (lane >> 2);
        #pragma unroll
        for (int nt = 0; nt < 4; nt++) {
            int n = bn + wn * 32 + nt * 8 + (lane & 3) * 2;
            float bx = bias[n], by = bias[n + 1];
            *(float2*)(C + (size_t)m0 * (2*D_MODEL) + D_MODEL + n) =
                make_float2(acc[mt][nt][0] + bx, acc[mt][nt][1] + by);
            *(float2*)(C + (size_t)(m0 + 8) * (2*D_MODEL) + D_MODEL + n) =
                make_float2(acc[mt][nt][2] + bx, acc[mt][nt][3] + by);
        }
    }
}

// ---------------------------------------------------------------------------
// Attention: 2 warps per line (4 heads each), 8 lanes/head, 12 dims/lane.
// Fused copy of main -> out[:, :768].
// ---------------------------------------------------------------------------
__global__ __launch_bounds__(256)
void attn_kernel(const __half* __restrict__ P, __half* __restrict__ ctx,
                 const float* __restrict__ mn, float* __restrict__ out)
{
    const int warp = threadIdx.x >> 5;
    const int lane = threadIdx.x & 31;
    const int n    = blockIdx.x * 4 + (warp >> 1);
    const int half = warp & 1;
    const int dimoff = half * 384 + (lane >> 3) * HD + (lane & 7) * 12;

    const float scale = rsqrtf((float)HD);

    float qf[12];
    {
        const uint2* qp = (const uint2*)(P + (size_t)(n + OVERLAP) * QKV_N + dimoff);
        #pragma unroll
        for (int t = 0; t < 3; t++) {
            uint2 u = qp[t];
            const __half2* h2 = (const __half2*)&u;
            #pragma unroll
            for (int j = 0; j < 2; j++) {
                float2 f = __half22float2(h2[j]);
                qf[t*4 + 2*j]     = f.x * scale;
                qf[t*4 + 2*j + 1] = f.y * scale;
            }
        }
    }

    float s[W_KEYS];
    #pragma unroll
    for (int w = 0; w < W_KEYS; w++) {
        int off = (w < 8) ? (-OVERLAP + GAP * w) : (GAP * (w - 7));
        const uint2* kp = (const uint2*)(P + (size_t)(n + OVERLAP + off) * QKV_N + D_MODEL + dimoff);
        float p = 0.f;
        #pragma unroll
        for (int t = 0; t < 3; t++) {
            uint2 u = kp[t];
            const __half2* h2 = (const __half2*)&u;
            #pragma unroll
            for (int j = 0; j < 2; j++) {
                float2 f = __half22float2(h2[j]);
                p = fmaf(qf[t*4 + 2*j],     f.x, p);
                p = fmaf(qf[t*4 + 2*j + 1], f.y, p);
            }
        }
        p += __shfl_xor_sync(0xffffffffu, p, 1);
        p += __shfl_xor_sync(0xffffffffu, p, 2);
        p += __shfl_xor_sync(0xffffffffu, p, 4);
        s[w] = p;
    }

    float m = s[0];
    #pragma unroll
    for (int w = 1; w < W_KEYS; w++) m = fmaxf(m, s[w]);
    float sum = 0.f;
    #pragma unroll
    for (int w = 0; w < W_KEYS; w++) { s[w] = __expf(s[w] - m); sum += s[w]; }
    float inv = 1.f / sum;

    float c[12];
    #pragma unroll
    for (int j = 0; j < 12; j++) c[j] = 0.f;
    #pragma unroll
    for (int w = 0; w < W_KEYS; w++) {
        int off = (w < 8) ? (-OVERLAP + GAP * w) : (GAP * (w - 7));
        const uint2* vp = (const uint2*)(P + (size_t)(n + OVERLAP + off) * QKV_N + 2*D_MODEL + dimoff);
        float p = s[w] * inv;
        #pragma unroll
        for (int t = 0; t < 3; t++) {
            uint2 u = vp[t];
            const __half2* h2 = (const __half2*)&u;
            #pragma unroll
            for (int j = 0; j < 2; j++) {
                float2 f = __half22float2(h2[j]);
                c[t*4 + 2*j]     = fmaf(p, f.x, c[t*4 + 2*j]);
                c[t*4 + 2*j + 1] = fmaf(p, f.y, c[t*4 + 2*j + 1]);
            }
        }
    }

    uint2* cp = (uint2*)(ctx + (size_t)n * D_MODEL + dimoff);
    #pragma unroll
    for (int t = 0; t < 3; t++) {
        uint2 u;
        __half2* h2 = (__half2*)&u;
        h2[0] = __floats2half2_rn(c[t*4 + 0], c[t*4 + 1]);
        h2[1] = __floats2half2_rn(c[t*4 + 2], c[t*4 + 3]);
        cp[t] = u;
    }

    {
        int b0 = blockIdx.x * 768 + threadIdx.x;
        #pragma unroll
        for (int i = 0; i < 3; i++) {
            int idx = b0 + i * 256;
            int row = idx / 192, c4 = idx % 192;
            ((float4*)(out + (size_t)row * 2 * D_MODEL))[c4] =
                ((const float4*)(mn + (size_t)row * D_MODEL))[c4];
        }
    }
}

// ---------------------------------------------------------------------------
extern "C" void kernel_launch(void* const* d_in, const int* in_sizes, int n_in,
                              void* d_out, int out_size)
{
    const float* mn   = (const float*)d_in[0];
    const float* bg   = (const float*)d_in[1];
    const float* ed   = (const float*)d_in[2];
    const float* wqkv = (const float*)d_in[3];
    const float* bqkv = (const float*)d_in[4];
    const float* wo   = (const float*)d_in[5];
    const float* bo   = (const float*)d_in[6];
    float* out = (float*)d_out;

    void *pP, *pc, *pw1, *pw2, *pcx;
    cudaGetSymbolAddress(&pP,  g_P);
    cudaGetSymbolAddress(&pc,  g_comb);
    cudaGetSymbolAddress(&pw1, g_w1);
    cudaGetSymbolAddress(&pw2, g_w2);
    cudaGetSymbolAddress(&pcx, g_ctx);

    cudaFuncSetAttribute(gemm1_fp16, cudaFuncAttributeMaxDynamicSharedMemorySize, GEMM1_SMEM);
    cudaFuncSetAttribute(gemm2_fp16, cudaFuncAttributeMaxDynamicSharedMemorySize, GEMM2_SMEM);

    // prep (fused conversions, MLP=4)
    prep_kernel<<<(PREP_TOTAL + 1023) / 1024, 256>>>(mn, bg, ed, wqkv, wo);

    // GEMM1: P = comb @ wqkv^T + bqkv  (Mpad=8320, N=2304) -> fp16 P
    {
        dim3 grid(QKV_N / 128, M_PAD / 128);
        gemm1_fp16<<<grid, 256, GEMM1_SMEM>>>(
            (const __half*)pc, (const __half*)pw1, bqkv, (__half*)pP);
    }
    // attention (+ fused main copy) -> ctx fp16
    attn_kernel<<<N_LINES / 4, 256>>>((const __half*)pP, (__half*)pcx, mn, out);

    // GEMM2: out[:,768:] = ctx @ wo^T + bo  (M=8192, N=768) -> fp32
    {
        dim3 grid(D_MODEL / 128, N_LINES / 64);
        gemm2_fp16<<<grid, 256, GEMM2_SMEM>>>(
            (const __half*)pcx, (const __half*)pw2, bo, out);
    }
}